// round 1
// baseline (speedup 1.0000x reference)
#include <cuda_runtime.h>
#include <cstdint>

#define H 256
#define NGRAPH 128
#define MAXN   20096
#define MAXEG  200064
#define MAXELG 400128

// ---------------- scratch (static device allocations; ~2.1 GB) ----------------
__device__ float g_hnode[MAXN * H];
__device__ float g_Abuf[MAXN * H];
__device__ float g_Bbuf[MAXN * H];
__device__ float g_h[MAXEG * H];
__device__ float g_h2[MAXEG * H];
__device__ float g_hpre[MAXEG * H];
__device__ float g_hidden[(size_t)MAXEG * 2 * H];
__device__ float g_m[(size_t)MAXELG * H];
__device__ float g_mmax[MAXEG * H];
__device__ float g_s[MAXEG * H];
__device__ float g_w[MAXEG * H];
__device__ float g_nbg[MAXEG * 4];
__device__ float g_ebg[MAXELG * 4];
__device__ float g_nodeemb[MAXN * H];
__device__ double g_bnacc[2 * H];
__device__ float g_gsum[NGRAPH * H];
__device__ float g_cnt[NGRAPH];

// ---------------- generic fp32 tiled GEMM: C = A[M,K] @ B[K,N] (+bias,+res,relu) ----
// flags: 1 = add bias[col], 2 = relu, 4 = add res[row*N+col]
__global__ __launch_bounds__(256) void sgemm_kernel(
    const float* __restrict__ A, const float* __restrict__ B,
    const float* __restrict__ bias, const float* __restrict__ res,
    float* __restrict__ C, int M, int N, int K, int flags)
{
    const int BM = 128, BN = 128, BK = 8, TM = 8, TN = 8;
    __shared__ float As[BK][BM];
    __shared__ float Bs[BK][BN];
    int tid = threadIdx.x;
    int bm = blockIdx.y * BM, bn = blockIdx.x * BN;
    int arow = tid >> 1, acol = (tid & 1) * 4;
    int brow = tid >> 5, bcol = (tid & 31) * 4;
    int tr = (tid >> 4) * TM, tc = (tid & 15) * TN;

    float acc[TM][TN];
#pragma unroll
    for (int i = 0; i < TM; i++)
#pragma unroll
        for (int j = 0; j < TN; j++) acc[i][j] = 0.f;

    bool arow_ok = (bm + arow) < M;
    const float* Aptr = A + (size_t)(bm + arow) * K + acol;

    for (int k0 = 0; k0 < K; k0 += BK) {
        float4 av = arow_ok ? *(const float4*)(Aptr + k0) : make_float4(0.f, 0.f, 0.f, 0.f);
        float4 bv = *(const float4*)(B + (size_t)(k0 + brow) * N + bn + bcol);
        As[acol + 0][arow] = av.x;
        As[acol + 1][arow] = av.y;
        As[acol + 2][arow] = av.z;
        As[acol + 3][arow] = av.w;
        *(float4*)&Bs[brow][bcol] = bv;
        __syncthreads();
#pragma unroll
        for (int k = 0; k < BK; k++) {
            float ra[TM], rb[TN];
#pragma unroll
            for (int i = 0; i < TM; i++) ra[i] = As[k][tr + i];
#pragma unroll
            for (int j = 0; j < TN; j++) rb[j] = Bs[k][tc + j];
#pragma unroll
            for (int i = 0; i < TM; i++)
#pragma unroll
                for (int j = 0; j < TN; j++) acc[i][j] = fmaf(ra[i], rb[j], acc[i][j]);
        }
        __syncthreads();
    }

    float bb[TN];
    if (flags & 1) {
#pragma unroll
        for (int j = 0; j < TN; j++) bb[j] = bias[bn + tc + j];
    }
#pragma unroll
    for (int i = 0; i < TM; i++) {
        int row = bm + tr + i;
        if (row >= M) continue;
        size_t off = (size_t)row * N + bn + tc;
        float v[TN];
#pragma unroll
        for (int j = 0; j < TN; j++) {
            v[j] = acc[i][j];
            if (flags & 1) v[j] += bb[j];
        }
        if (flags & 4) {
            float4 r0 = *(const float4*)(res + off);
            float4 r1 = *(const float4*)(res + off + 4);
            v[0] += r0.x; v[1] += r0.y; v[2] += r0.z; v[3] += r0.w;
            v[4] += r1.x; v[5] += r1.y; v[6] += r1.z; v[7] += r1.w;
        }
        if (flags & 2) {
#pragma unroll
            for (int j = 0; j < TN; j++) v[j] = fmaxf(v[j], 0.f);
        }
        *(float4*)(C + off) = make_float4(v[0], v[1], v[2], v[3]);
        *(float4*)(C + off + 4) = make_float4(v[4], v[5], v[6], v[7]);
    }
}

// ---------------- tiny [E,4]@[4,4]+b projection -------------------------------
__global__ void basis4_kernel(const float* __restrict__ in, const float* __restrict__ W,
                              const float* __restrict__ b, float* __restrict__ out, int E)
{
    int e = blockIdx.x * blockDim.x + threadIdx.x;
    if (e >= E) return;
    float4 x = *(const float4*)(in + (size_t)e * 4);
    float o0 = b[0] + x.x * W[0] + x.y * W[4] + x.z * W[8]  + x.w * W[12];
    float o1 = b[1] + x.x * W[1] + x.y * W[5] + x.z * W[9]  + x.w * W[13];
    float o2 = b[2] + x.x * W[2] + x.y * W[6] + x.z * W[10] + x.w * W[14];
    float o3 = b[3] + x.x * W[3] + x.y * W[7] + x.z * W[11] + x.w * W[15];
    *(float4*)(out + (size_t)e * 4) = make_float4(o0, o1, o2, o3);
}

// ---------------- fused first-message: h = A[src]+B[dst]+ea@Wc+xl@Wd+b --------
#define MEPB 16
__global__ __launch_bounds__(256) void msg_edge_kernel(
    const float* __restrict__ Abuf, const float* __restrict__ Bbuf,
    const float* __restrict__ ea, const float* __restrict__ xlg,
    const float* __restrict__ Wc, const float* __restrict__ Wd,
    const float* __restrict__ bmsg,
    const int* __restrict__ srcg, const int* __restrict__ dstg,
    float* __restrict__ h, int Eg)
{
    __shared__ float sWc[16 * H];
    __shared__ float sWd[4 * H];
    __shared__ float sb[H];
    __shared__ float sea[MEPB][16];
    __shared__ float sxl[MEPB][4];
    int tid = threadIdx.x;
    for (int i = tid; i < 16 * H; i += 256) sWc[i] = Wc[i];
    for (int i = tid; i < 4 * H; i += 256) sWd[i] = Wd[i];
    sb[tid] = bmsg[tid];
    int e0 = blockIdx.x * MEPB;
    for (int i = tid; i < MEPB * 16; i += 256) {
        int e = e0 + i / 16;
        if (e < Eg) sea[i / 16][i % 16] = ea[(size_t)e * 16 + (i % 16)];
    }
    for (int i = tid; i < MEPB * 4; i += 256) {
        int e = e0 + i / 4;
        if (e < Eg) sxl[i / 4][i % 4] = xlg[(size_t)e * 4 + (i % 4)];
    }
    __syncthreads();
    int c = tid;
    for (int i = 0; i < MEPB; i++) {
        int e = e0 + i;
        if (e >= Eg) break;
        int s = srcg[e], d = dstg[e];
        float v = Abuf[(size_t)s * H + c] + Bbuf[(size_t)d * H + c] + sb[c];
#pragma unroll
        for (int k = 0; k < 16; k++) v = fmaf(sea[i][k], sWc[k * H + c], v);
#pragma unroll
        for (int k = 0; k < 4; k++) v = fmaf(sxl[i][k], sWd[k * H + c], v);
        h[(size_t)e * H + c] = v;
    }
}

// ---------------- GENConv pass A: m = relu(x[src]+nb[src]+eb)+eps; seg-max ----
#define AEPB 8
__global__ __launch_bounds__(256) void genA_kernel(
    const float* __restrict__ x, const float* __restrict__ nbg, const float* __restrict__ ebg,
    const float* __restrict__ Wnb, const float* __restrict__ bnb,
    const float* __restrict__ Web, const float* __restrict__ beb,
    const int* __restrict__ src, const int* __restrict__ dst,
    float* __restrict__ m, float* __restrict__ mmax, int Elg)
{
    __shared__ float sWn[4 * H], sWe[4 * H], sbn[H], sbe[H];
    int tid = threadIdx.x;
    for (int i = tid; i < 4 * H; i += 256) { sWn[i] = Wnb[i]; sWe[i] = Web[i]; }
    sbn[tid] = bnb[tid];
    sbe[tid] = beb[tid];
    __syncthreads();
    int c = tid;
    int e0 = blockIdx.x * AEPB;
    for (int i = 0; i < AEPB; i++) {
        int e = e0 + i;
        if (e >= Elg) break;
        int s = src[e], d = dst[e];
        float4 nv = *(const float4*)(nbg + (size_t)s * 4);
        float4 ev = *(const float4*)(ebg + (size_t)e * 4);
        float nbv = sbn[c];
        nbv = fmaf(nv.x, sWn[c], nbv);
        nbv = fmaf(nv.y, sWn[H + c], nbv);
        nbv = fmaf(nv.z, sWn[2 * H + c], nbv);
        nbv = fmaf(nv.w, sWn[3 * H + c], nbv);
        float ebv = sbe[c];
        ebv = fmaf(ev.x, sWe[c], ebv);
        ebv = fmaf(ev.y, sWe[H + c], ebv);
        ebv = fmaf(ev.z, sWe[2 * H + c], ebv);
        ebv = fmaf(ev.w, sWe[3 * H + c], ebv);
        float xv = x[(size_t)s * H + c];
        float mv = fmaxf(xv + nbv + ebv, 0.f) + 1e-7f;
        m[(size_t)e * H + c] = mv;
        // all mv > 0 -> positive-float ordering == int ordering; mmax init 0
        atomicMax((int*)(mmax + (size_t)d * H + c), __float_as_int(mv));
    }
}

// ---------------- GENConv pass B: e = exp(m - mmax[dst]); seg-sum(e), seg-sum(e*m)
__global__ __launch_bounds__(256) void genB_kernel(
    const float* __restrict__ m, const float* __restrict__ mmax,
    const int* __restrict__ dst,
    float* __restrict__ svec, float* __restrict__ wvec, int Elg)
{
    int c = threadIdx.x;
    int e0 = blockIdx.x * AEPB;
    for (int i = 0; i < AEPB; i++) {
        int e = e0 + i;
        if (e >= Elg) break;
        int d = dst[e];
        float mv = m[(size_t)e * H + c];
        float mx = mmax[(size_t)d * H + c];
        float ev = expf(mv - mx);
        atomicAdd(svec + (size_t)d * H + c, ev);
        atomicAdd(wvec + (size_t)d * H + c, ev * mv);
    }
}

// ---------------- GENConv pass D: hpre = x + wsum/(s+1e-16) -------------------
__global__ void genD_kernel(const float* __restrict__ x, const float* __restrict__ svec,
                            const float* __restrict__ wvec, float* __restrict__ out)
{
    size_t i = (size_t)blockIdx.x * H + threadIdx.x;
    out[i] = x[i] + wvec[i] / (svec[i] + 1e-16f);
}

// ---------------- BatchNorm batch statistics ----------------------------------
__global__ void bn_stats_kernel(const float* __restrict__ h, int M, double* __restrict__ acc)
{
    int c = threadIdx.x;
    float s = 0.f, s2 = 0.f;
    for (int r = blockIdx.x; r < M; r += gridDim.x) {
        float v = h[(size_t)r * H + c];
        s += v;
        s2 = fmaf(v, v, s2);
    }
    atomicAdd(&acc[c], (double)s);
    atomicAdd(&acc[H + c], (double)s2);
}

__global__ void bn_apply_kernel(const float* __restrict__ h, const double* __restrict__ acc,
                                const float* __restrict__ gamma, const float* __restrict__ beta,
                                float* __restrict__ out, int M, int do_relu)
{
    int c = threadIdx.x;
    double mean_d = acc[c] / (double)M;
    double var_d = acc[H + c] / (double)M - mean_d * mean_d;
    float mean = (float)mean_d;
    float inv = rsqrtf((float)var_d + 1e-5f);
    float ga = gamma[c], be = beta[c];
    for (int r = blockIdx.x; r < M; r += gridDim.x) {
        size_t i = (size_t)r * H + c;
        float v = fmaf((h[i] - mean) * inv, ga, be);
        if (do_relu) v = fmaxf(v, 0.f);
        out[i] = v;
    }
}

// ---------------- final scatter / pooling / prediction ------------------------
__global__ __launch_bounds__(256) void scatter_kernel(const float* __restrict__ hbn,
                                                      const int* __restrict__ dstg,
                                                      float* __restrict__ node_emb, int Eg)
{
    int c = threadIdx.x;
    int e0 = blockIdx.x * AEPB;
    for (int i = 0; i < AEPB; i++) {
        int e = e0 + i;
        if (e >= Eg) break;
        atomicAdd(node_emb + (size_t)dstg[e] * H + c, hbn[(size_t)e * H + c]);
    }
}

__global__ void pool_kernel(const float* __restrict__ node_emb, const int* __restrict__ batch,
                            float* __restrict__ gsum, float* __restrict__ cnt)
{
    int n = blockIdx.x;
    int c = threadIdx.x;
    int b = batch[n];
    atomicAdd(gsum + (size_t)b * H + c, node_emb[(size_t)n * H + c]);
    if (c == 0) atomicAdd(&cnt[b], 1.0f);
}

__global__ void predict_kernel(const float* __restrict__ gsum, const float* __restrict__ cnt,
                               const float* __restrict__ Wp, const float* __restrict__ bp,
                               float* __restrict__ out)
{
    int g = blockIdx.x, c = threadIdx.x;
    float v = gsum[(size_t)g * H + c] * Wp[c];
    __shared__ float red[8];
#pragma unroll
    for (int o = 16; o > 0; o >>= 1) v += __shfl_down_sync(0xffffffffu, v, o);
    if ((c & 31) == 0) red[c >> 5] = v;
    __syncthreads();
    if (c == 0) {
        float t = 0.f;
#pragma unroll
        for (int i = 0; i < 8; i++) t += red[i];
        out[g] = t / fmaxf(cnt[g], 1.0f) + bp[0];
    }
}

// -------------------------------------------------------------------------------
static float* symaddr(const void* sym)
{
    void* p = nullptr;
    cudaGetSymbolAddress(&p, sym);
    return (float*)p;
}

static void run_gemm(const float* A, const float* B, const float* bias, const float* res,
                     float* C, int M, int N, int K, int flags)
{
    dim3 grid(N / 128, (M + 127) / 128);
    sgemm_kernel<<<grid, 256>>>(A, B, bias, res, C, M, N, K, flags);
}

extern "C" void kernel_launch(void* const* d_in, const int* in_sizes, int n_in,
                              void* d_out, int out_size)
{
    const float* x_g       = (const float*)d_in[0];
    const float* ea_g      = (const float*)d_in[1];
    const float* x_lg      = (const float*)d_in[2];
    const float* edb       = (const float*)d_in[3];
    const float* ea_lg     = (const float*)d_in[4];
    const float* W_enc     = (const float*)d_in[5];
    const float* b_enc     = (const float*)d_in[6];
    const float* W_msg     = (const float*)d_in[7];
    const float* b_msg     = (const float*)d_in[8];
    const float* Wg_nb     = (const float*)d_in[9];
    const float* bg_nb     = (const float*)d_in[10];
    const float* Wg_eb     = (const float*)d_in[11];
    const float* bg_eb     = (const float*)d_in[12];
    const float* Wl_nb     = (const float*)d_in[13];
    const float* bl_nb     = (const float*)d_in[14];
    const float* Wl_eb     = (const float*)d_in[15];
    const float* bl_eb     = (const float*)d_in[16];
    const float* W1        = (const float*)d_in[17];
    const float* b1        = (const float*)d_in[18];
    const float* W2        = (const float*)d_in[19];
    const float* b2        = (const float*)d_in[20];
    const float* bn_gamma  = (const float*)d_in[21];
    const float* bn_beta   = (const float*)d_in[22];
    const float* W_pred    = (const float*)d_in[23];
    const float* b_pred    = (const float*)d_in[24];
    const int*   eig       = (const int*)d_in[25];
    const int*   eil       = (const int*)d_in[26];
    const int*   batch     = (const int*)d_in[27];

    int N   = in_sizes[0] / 16;   // 20000
    int Eg  = in_sizes[1] / 16;   // 200000
    int Elg = in_sizes[4] / 4;    // 400000
    const int L = 4;

    float* p_hnode  = symaddr(g_hnode);
    float* p_A      = symaddr(g_Abuf);
    float* p_B      = symaddr(g_Bbuf);
    float* p_h      = symaddr(g_h);
    float* p_h2     = symaddr(g_h2);
    float* p_hpre   = symaddr(g_hpre);
    float* p_hidden = symaddr(g_hidden);
    float* p_m      = symaddr(g_m);
    float* p_mmax   = symaddr(g_mmax);
    float* p_s      = symaddr(g_s);
    float* p_w      = symaddr(g_w);
    float* p_nbg    = symaddr(g_nbg);
    float* p_ebg    = symaddr(g_ebg);
    float* p_ne     = symaddr(g_nodeemb);
    double* p_bnacc = (double*)symaddr(g_bnacc);
    float* p_gsum   = symaddr(g_gsum);
    float* p_cnt    = symaddr(g_cnt);

    const int* src_g = eig;
    const int* dst_g = eig + Eg;
    const int* src_l = eil;
    const int* dst_l = eil + Elg;

    // --- encoders + first message embedding ---
    run_gemm(x_g, W_enc, b_enc, nullptr, p_hnode, N, H, 16, 1);
    run_gemm(p_hnode, W_msg,            nullptr, nullptr, p_A, N, H, H, 0);
    run_gemm(p_hnode, W_msg + 256 * H,  nullptr, nullptr, p_B, N, H, H, 0);
    basis4_kernel<<<(Eg + 255) / 256, 256>>>(edb,   Wg_nb, bg_nb, p_nbg, Eg);
    basis4_kernel<<<(Elg + 255) / 256, 256>>>(ea_lg, Wg_eb, bg_eb, p_ebg, Elg);
    msg_edge_kernel<<<(Eg + MEPB - 1) / MEPB, 256>>>(
        p_A, p_B, ea_g, x_lg, W_msg + 512 * H, W_msg + 528 * H, b_msg,
        src_g, dst_g, p_h, Eg);

    // --- 4 GENConv layers ---
    for (int l = 0; l < L; l++) {
        const float* xptr = p_h;
        if (l > 0) {
            cudaMemsetAsync(p_bnacc, 0, 2 * H * sizeof(double));
            bn_stats_kernel<<<1024, 256>>>(p_h, Eg, p_bnacc);
            bn_apply_kernel<<<2048, 256>>>(p_h, p_bnacc,
                                           bn_gamma + (l - 1) * H, bn_beta + (l - 1) * H,
                                           p_h2, Eg, 1);
            xptr = p_h2;
        }
        cudaMemsetAsync(p_mmax, 0, (size_t)Eg * H * sizeof(float));
        cudaMemsetAsync(p_s,    0, (size_t)Eg * H * sizeof(float));
        cudaMemsetAsync(p_w,    0, (size_t)Eg * H * sizeof(float));
        genA_kernel<<<(Elg + AEPB - 1) / AEPB, 256>>>(
            xptr, p_nbg, p_ebg,
            Wl_nb + l * 4 * H, bl_nb + l * H,
            Wl_eb + l * 4 * H, bl_eb + l * H,
            src_l, dst_l, p_m, p_mmax, Elg);
        genB_kernel<<<(Elg + AEPB - 1) / AEPB, 256>>>(p_m, p_mmax, dst_l, p_s, p_w, Elg);
        genD_kernel<<<Eg, 256>>>(xptr, p_s, p_w, p_hpre);
        run_gemm(p_hpre,   W1 + (size_t)l * H * 2 * H, b1 + l * 2 * H, nullptr,
                 p_hidden, Eg, 2 * H, H, 1 | 2);
        run_gemm(p_hidden, W2 + (size_t)l * 2 * H * H, b2 + l * H,
                 (l > 0) ? p_h : nullptr,
                 p_h, Eg, H, 2 * H, (l > 0) ? (1 | 4) : 1);
    }

    // --- final BN (no relu) ---
    cudaMemsetAsync(p_bnacc, 0, 2 * H * sizeof(double));
    bn_stats_kernel<<<1024, 256>>>(p_h, Eg, p_bnacc);
    bn_apply_kernel<<<2048, 256>>>(p_h, p_bnacc, bn_gamma + 3 * H, bn_beta + 3 * H,
                                   p_h2, Eg, 0);

    // --- scatter to nodes, pool per graph, predict ---
    cudaMemsetAsync(p_ne,   0, (size_t)N * H * sizeof(float));
    cudaMemsetAsync(p_gsum, 0, NGRAPH * H * sizeof(float));
    cudaMemsetAsync(p_cnt,  0, NGRAPH * sizeof(float));
    scatter_kernel<<<(Eg + AEPB - 1) / AEPB, 256>>>(p_h2, dst_g, p_ne, Eg);
    pool_kernel<<<N, 256>>>(p_ne, batch, p_gsum, p_cnt);
    predict_kernel<<<NGRAPH, 256>>>(p_gsum, p_cnt, W_pred, b_pred, (float*)d_out);
}

// round 3
// speedup vs baseline: 1.5424x; 1.5424x over previous
#include <cuda_runtime.h>
#include <cuda_bf16.h>
#include <cstdint>

#define H 256
#define NGRAPH 128
#define MAXN   20096
#define MAXEG  200064
#define MAXELG 400128

// ---------------- scratch ----------------
__device__ float g_Abuf[(size_t)MAXN * H];
__device__ float g_Bbuf[(size_t)MAXN * H];
__device__ float g_h[(size_t)MAXEG * H];
__device__ float g_h2[(size_t)MAXEG * H];
__device__ float g_m[(size_t)MAXELG * H];
__device__ float g_mmax[(size_t)MAXEG * H];
__device__ float g_s[(size_t)MAXEG * H];
__device__ float g_w[(size_t)MAXEG * H];
__device__ float g_nbg[(size_t)MAXEG * 4];
__device__ float g_ebg[(size_t)MAXELG * 4];
__device__ float g_nodeemb[(size_t)MAXN * H];
__device__ double g_bnacc[2 * H];
__device__ float g_gsum[NGRAPH * H];
__device__ float g_cnt[NGRAPH];

// bf16 split buffers (padded to tile multiples; OOB rows stay finite)
__device__ __nv_bfloat16 g_node_hi[(size_t)MAXN * H];
__device__ __nv_bfloat16 g_node_lo[(size_t)MAXN * H];
__device__ __nv_bfloat16 g_act_hi[(size_t)MAXEG * H];
__device__ __nv_bfloat16 g_act_lo[(size_t)MAXEG * H];
__device__ __nv_bfloat16 g_hid_hi[(size_t)MAXEG * 2 * H];
__device__ __nv_bfloat16 g_hid_lo[(size_t)MAXEG * 2 * H];

// transposed/split weights arena (elements)
#define OFF_WA  0
#define OFF_WB  65536
#define OFF_W1T 131072
#define OFF_W2T (131072 + 4 * 131072)
#define WT_TOTAL (OFF_W2T + 4 * 131072)
__device__ __nv_bfloat16 g_wthi[WT_TOTAL];
__device__ __nv_bfloat16 g_wtlo[WT_TOTAL];

// ======================= helpers =======================
__device__ __forceinline__ uint32_t smem_u32(const void* p) {
    uint32_t a;
    asm("{ .reg .u64 t; cvta.to.shared.u64 t, %1; cvt.u32.u64 %0, t; }" : "=r"(a) : "l"(p));
    return a;
}
#define CP16(dst, src) \
    asm volatile("cp.async.cg.shared.global [%0], [%1], 16;" :: "r"(dst), "l"(src) : "memory")
#define CP_COMMIT() asm volatile("cp.async.commit_group;" ::: "memory")
#define CP_WAIT2()  asm volatile("cp.async.wait_group 2;" ::: "memory")

__device__ __forceinline__ void ldm4(uint32_t (&r)[4], uint32_t addr) {
    asm volatile("ldmatrix.sync.aligned.m8n8.x4.shared.b16 {%0,%1,%2,%3}, [%4];"
                 : "=r"(r[0]), "=r"(r[1]), "=r"(r[2]), "=r"(r[3]) : "r"(addr));
}
__device__ __forceinline__ void mma_bf16(float (&d)[4], const uint32_t (&a)[4], const uint32_t* b) {
    asm volatile(
        "mma.sync.aligned.m16n8k16.row.col.f32.bf16.bf16.f32 "
        "{%0,%1,%2,%3}, {%4,%5,%6,%7}, {%8,%9}, {%0,%1,%2,%3};"
        : "+f"(d[0]), "+f"(d[1]), "+f"(d[2]), "+f"(d[3])
        : "r"(a[0]), "r"(a[1]), "r"(a[2]), "r"(a[3]), "r"(b[0]), "r"(b[1]));
}
__device__ __forceinline__ void split2(float v, __nv_bfloat16& hi, __nv_bfloat16& lo) {
    hi = __float2bfloat16(v);
    lo = __float2bfloat16(v - __bfloat162float(hi));
}

// ======================= mma.sync split-bf16 GEMM =======================
// C[M,N] = A[M,K] @ W[K,N]; A as (Ahi,Alo) bf16 [M,K] row-major,
// W transposed as (Bhi,Blo) bf16 [N,K] row-major.
// flags: 1=bias, 2=relu, 4=residual(fp32 [M,N]), 8=split-out bf16 (else fp32 out)
// CTA tile 128x128, BK=32, 4 stages. Rows padded to 80B in smem (conflict-free ldmatrix).
#define RB 80                      // row stride bytes in smem (32 bf16 -> 80B padded)
#define TILE_B (128 * RB)          // 10240 per tile
#define SO_AHI 0
#define SO_ALO (1 * TILE_B)
#define SO_BHI (2 * TILE_B)
#define SO_BLO (3 * TILE_B)
#define STAGE_B (4 * TILE_B)       // 40960
#define NSTAGE 4
#define GEMM_SMEM (NSTAGE * STAGE_B)  // 163840

__device__ __forceinline__ void load_stage(uint32_t sbase,
    const __nv_bfloat16* __restrict__ A_hi, const __nv_bfloat16* __restrict__ A_lo,
    const __nv_bfloat16* __restrict__ B_hi, const __nv_bfloat16* __restrict__ B_lo,
    int K, int m0, int n0, int k0, int tid)
{
#pragma unroll
    for (int i = 0; i < 2; i++) {
        int g = tid + i * 256;             // 0..511
        int row = g >> 2, ch = g & 3;
        uint32_t so = (uint32_t)row * RB + (uint32_t)ch * 16;
        size_t ao = (size_t)(m0 + row) * K + k0 + ch * 8;
        size_t bo = (size_t)(n0 + row) * K + k0 + ch * 8;
        CP16(sbase + SO_AHI + so, A_hi + ao);
        CP16(sbase + SO_ALO + so, A_lo + ao);
        CP16(sbase + SO_BHI + so, B_hi + bo);
        CP16(sbase + SO_BLO + so, B_lo + bo);
    }
}

__global__ __launch_bounds__(256, 1) void mma_gemm_kernel(
    const __nv_bfloat16* __restrict__ Ahi, const __nv_bfloat16* __restrict__ Alo,
    const __nv_bfloat16* __restrict__ Bhi, const __nv_bfloat16* __restrict__ Blo,
    const float* __restrict__ bias, const float* __restrict__ res,
    float* __restrict__ Cf, __nv_bfloat16* __restrict__ Chi, __nv_bfloat16* __restrict__ Clo,
    int M, int N, int K, int flags)
{
    extern __shared__ __align__(128) char smem[];
    uint32_t sb = smem_u32(smem);
    int tid = threadIdx.x;
    int wid = tid >> 5, lane = tid & 31;
    int m0 = blockIdx.x * 128, n0 = blockIdx.y * 128;
    int nk = K >> 5;

    // prologue: stages 0..2
#pragma unroll
    for (int s = 0; s < 3; s++) {
        load_stage(sb + s * STAGE_B, Ahi, Alo, Bhi, Blo, K, m0, n0, s * 32, tid);
        CP_COMMIT();
    }

    float acc[2][8][4];
#pragma unroll
    for (int i = 0; i < 2; i++)
#pragma unroll
        for (int j = 0; j < 8; j++)
#pragma unroll
            for (int q = 0; q < 4; q++) acc[i][j][q] = 0.f;

    int mo = (wid >> 1) * 32, no = (wid & 1) * 64;
    int a_row = mo + (lane & 15);
    int a_k8  = lane >> 4;                       // 0/1
    int b_row = ((lane >> 4) << 3) + (lane & 7); // 0..15 within j-block
    int b_k8  = (lane >> 3) & 1;

    for (int k = 0; k < nk; k++) {
        CP_WAIT2();
        __syncthreads();
        uint32_t base = sb + (uint32_t)(k & 3) * STAGE_B;
#pragma unroll
        for (int k16 = 0; k16 < 2; k16++) {
            int kk8 = k16 * 2;
            uint32_t ah[2][4], al[2][4], bh[4][4], bl[4][4];
#pragma unroll
            for (int i = 0; i < 2; i++) {
                uint32_t aaddr = base + SO_AHI + (uint32_t)(a_row + i * 16) * RB
                               + (uint32_t)(kk8 + a_k8) * 16;
                ldm4(ah[i], aaddr);
                ldm4(al[i], aaddr + (SO_ALO - SO_AHI));
            }
#pragma unroll
            for (int j = 0; j < 4; j++) {
                uint32_t baddr = base + SO_BHI + (uint32_t)(no + j * 16 + b_row) * RB
                               + (uint32_t)(kk8 + b_k8) * 16;
                ldm4(bh[j], baddr);
                ldm4(bl[j], baddr + (SO_BLO - SO_BHI));
            }
#pragma unroll
            for (int i = 0; i < 2; i++)
#pragma unroll
                for (int j = 0; j < 4; j++) {
                    mma_bf16(acc[i][2 * j],     ah[i], &bh[j][0]);
                    mma_bf16(acc[i][2 * j + 1], ah[i], &bh[j][2]);
                    mma_bf16(acc[i][2 * j],     ah[i], &bl[j][0]);
                    mma_bf16(acc[i][2 * j + 1], ah[i], &bl[j][2]);
                    mma_bf16(acc[i][2 * j],     al[i], &bh[j][0]);
                    mma_bf16(acc[i][2 * j + 1], al[i], &bh[j][2]);
                }
        }
        int kn = k + 3;
        if (kn < nk)
            load_stage(sb + (uint32_t)(kn & 3) * STAGE_B, Ahi, Alo, Bhi, Blo,
                       K, m0, n0, kn * 32, tid);
        CP_COMMIT();
    }

    // epilogue
#pragma unroll
    for (int i = 0; i < 2; i++) {
        int r0 = m0 + mo + i * 16 + (lane >> 2);
#pragma unroll
        for (int half = 0; half < 2; half++) {
            int r = r0 + half * 8;
            if (r >= M) continue;
#pragma unroll
            for (int nb = 0; nb < 8; nb++) {
                int col = n0 + no + nb * 8 + 2 * (lane & 3);
                float v0 = acc[i][nb][half * 2 + 0];
                float v1 = acc[i][nb][half * 2 + 1];
                if (flags & 1) { v0 += bias[col]; v1 += bias[col + 1]; }
                if (flags & 4) {
                    float2 t = *(const float2*)(res + (size_t)r * N + col);
                    v0 += t.x; v1 += t.y;
                }
                if (flags & 2) { v0 = fmaxf(v0, 0.f); v1 = fmaxf(v1, 0.f); }
                if (flags & 8) {
                    __nv_bfloat16 h0, l0, h1, l1;
                    split2(v0, h0, l0);
                    split2(v1, h1, l1);
                    *(__nv_bfloat162*)(Chi + (size_t)r * N + col) = __halves2bfloat162(h0, h1);
                    *(__nv_bfloat162*)(Clo + (size_t)r * N + col) = __halves2bfloat162(l0, l1);
                } else {
                    *(float2*)(Cf + (size_t)r * N + col) = make_float2(v0, v1);
                }
            }
        }
    }
}

// ---------------- weight transpose+split: W[K,N] -> T[N,K] hi/lo --------------
__global__ void tsplit_kernel(const float* __restrict__ W,
                              __nv_bfloat16* __restrict__ thi, __nv_bfloat16* __restrict__ tlo,
                              int K, int N)
{
    int idx = blockIdx.x * 256 + threadIdx.x;
    if (idx >= K * N) return;
    int k = idx / N, n = idx % N;
    __nv_bfloat16 hi, lo;
    split2(W[idx], hi, lo);
    thi[(size_t)n * K + k] = hi;
    tlo[(size_t)n * K + k] = lo;
}

// ---------------- node encoder -------------------------------------------------
__global__ void enc_kernel(const float* __restrict__ xg, const float* __restrict__ W,
                           const float* __restrict__ b,
                           __nv_bfloat16* __restrict__ hi, __nv_bfloat16* __restrict__ lo)
{
    __shared__ float sx[16];
    int n = blockIdx.x, c = threadIdx.x;
    if (c < 16) sx[c] = xg[(size_t)n * 16 + c];
    __syncthreads();
    float v = b[c];
#pragma unroll
    for (int k = 0; k < 16; k++) v = fmaf(sx[k], W[k * H + c], v);
    __nv_bfloat16 h, l;
    split2(v, h, l);
    hi[(size_t)n * H + c] = h;
    lo[(size_t)n * H + c] = l;
}

// ---------------- tiny [E,4]@[4,4]+b projection -------------------------------
__global__ void basis4_kernel(const float* __restrict__ in, const float* __restrict__ W,
                              const float* __restrict__ b, float* __restrict__ out, int E)
{
    int e = blockIdx.x * blockDim.x + threadIdx.x;
    if (e >= E) return;
    float4 x = *(const float4*)(in + (size_t)e * 4);
    float o0 = b[0] + x.x * W[0] + x.y * W[4] + x.z * W[8]  + x.w * W[12];
    float o1 = b[1] + x.x * W[1] + x.y * W[5] + x.z * W[9]  + x.w * W[13];
    float o2 = b[2] + x.x * W[2] + x.y * W[6] + x.z * W[10] + x.w * W[14];
    float o3 = b[3] + x.x * W[3] + x.y * W[7] + x.z * W[11] + x.w * W[15];
    *(float4*)(out + (size_t)e * 4) = make_float4(o0, o1, o2, o3);
}

// ---------------- fused first-message ----------------------------------------
#define MEPB 16
__global__ __launch_bounds__(256) void msg_edge_kernel(
    const float* __restrict__ Abuf, const float* __restrict__ Bbuf,
    const float* __restrict__ ea, const float* __restrict__ xlg,
    const float* __restrict__ Wc, const float* __restrict__ Wd,
    const float* __restrict__ bmsg,
    const int* __restrict__ srcg, const int* __restrict__ dstg,
    float* __restrict__ h, int Eg)
{
    __shared__ float sWc[16 * H];
    __shared__ float sWd[4 * H];
    __shared__ float sb[H];
    __shared__ float sea[MEPB][16];
    __shared__ float sxl[MEPB][4];
    int tid = threadIdx.x;
    for (int i = tid; i < 16 * H; i += 256) sWc[i] = Wc[i];
    for (int i = tid; i < 4 * H; i += 256) sWd[i] = Wd[i];
    sb[tid] = bmsg[tid];
    int e0 = blockIdx.x * MEPB;
    for (int i = tid; i < MEPB * 16; i += 256) {
        int e = e0 + i / 16;
        if (e < Eg) sea[i / 16][i % 16] = ea[(size_t)e * 16 + (i % 16)];
    }
    for (int i = tid; i < MEPB * 4; i += 256) {
        int e = e0 + i / 4;
        if (e < Eg) sxl[i / 4][i % 4] = xlg[(size_t)e * 4 + (i % 4)];
    }
    __syncthreads();
    int c = tid;
    for (int i = 0; i < MEPB; i++) {
        int e = e0 + i;
        if (e >= Eg) break;
        int s = srcg[e], d = dstg[e];
        float v = Abuf[(size_t)s * H + c] + Bbuf[(size_t)d * H + c] + sb[c];
#pragma unroll
        for (int k = 0; k < 16; k++) v = fmaf(sea[i][k], sWc[k * H + c], v);
#pragma unroll
        for (int k = 0; k < 4; k++) v = fmaf(sxl[i][k], sWd[k * H + c], v);
        h[(size_t)e * H + c] = v;
    }
}

// ---------------- GENConv pass A ----------------------------------------------
#define AEPB 8
__global__ __launch_bounds__(256) void genA_kernel(
    const float* __restrict__ x, const float* __restrict__ nbg, const float* __restrict__ ebg,
    const float* __restrict__ Wnb, const float* __restrict__ bnb,
    const float* __restrict__ Web, const float* __restrict__ beb,
    const int* __restrict__ src, const int* __restrict__ dst,
    float* __restrict__ m, float* __restrict__ mmax, int Elg)
{
    __shared__ float sWn[4 * H], sWe[4 * H], sbn[H], sbe[H];
    int tid = threadIdx.x;
    for (int i = tid; i < 4 * H; i += 256) { sWn[i] = Wnb[i]; sWe[i] = Web[i]; }
    sbn[tid] = bnb[tid];
    sbe[tid] = beb[tid];
    __syncthreads();
    int c = tid;
    int e0 = blockIdx.x * AEPB;
    for (int i = 0; i < AEPB; i++) {
        int e = e0 + i;
        if (e >= Elg) break;
        int s = src[e], d = dst[e];
        float4 nv = *(const float4*)(nbg + (size_t)s * 4);
        float4 ev = *(const float4*)(ebg + (size_t)e * 4);
        float nbv = sbn[c];
        nbv = fmaf(nv.x, sWn[c], nbv);
        nbv = fmaf(nv.y, sWn[H + c], nbv);
        nbv = fmaf(nv.z, sWn[2 * H + c], nbv);
        nbv = fmaf(nv.w, sWn[3 * H + c], nbv);
        float ebv = sbe[c];
        ebv = fmaf(ev.x, sWe[c], ebv);
        ebv = fmaf(ev.y, sWe[H + c], ebv);
        ebv = fmaf(ev.z, sWe[2 * H + c], ebv);
        ebv = fmaf(ev.w, sWe[3 * H + c], ebv);
        float xv = x[(size_t)s * H + c];
        float mv = fmaxf(xv + nbv + ebv, 0.f) + 1e-7f;
        m[(size_t)e * H + c] = mv;
        atomicMax((int*)(mmax + (size_t)d * H + c), __float_as_int(mv));
    }
}

// ---------------- GENConv pass B ----------------------------------------------
__global__ __launch_bounds__(256) void genB_kernel(
    const float* __restrict__ m, const float* __restrict__ mmax,
    const int* __restrict__ dst,
    float* __restrict__ svec, float* __restrict__ wvec, int Elg)
{
    int c = threadIdx.x;
    int e0 = blockIdx.x * AEPB;
    for (int i = 0; i < AEPB; i++) {
        int e = e0 + i;
        if (e >= Elg) break;
        int d = dst[e];
        float mv = m[(size_t)e * H + c];
        float mx = mmax[(size_t)d * H + c];
        float ev = expf(mv - mx);
        atomicAdd(svec + (size_t)d * H + c, ev);
        atomicAdd(wvec + (size_t)d * H + c, ev * mv);
    }
}

// ---------------- GENConv pass D: hpre = x + w/(s+eps) -> split bf16 ---------
__global__ void genD_kernel(const float* __restrict__ x, const float* __restrict__ svec,
                            const float* __restrict__ wvec,
                            __nv_bfloat16* __restrict__ ahi, __nv_bfloat16* __restrict__ alo)
{
    size_t i = (size_t)blockIdx.x * H + threadIdx.x;
    float v = x[i] + wvec[i] / (svec[i] + 1e-16f);
    __nv_bfloat16 h, l;
    split2(v, h, l);
    ahi[i] = h;
    alo[i] = l;
}

// ---------------- BatchNorm ----------------------------------------------------
__global__ void bn_stats_kernel(const float* __restrict__ h, int M, double* __restrict__ acc)
{
    int c = threadIdx.x;
    float s = 0.f, s2 = 0.f;
    for (int r = blockIdx.x; r < M; r += gridDim.x) {
        float v = h[(size_t)r * H + c];
        s += v;
        s2 = fmaf(v, v, s2);
    }
    atomicAdd(&acc[c], (double)s);
    atomicAdd(&acc[H + c], (double)s2);
}

__global__ void bn_apply_kernel(const float* __restrict__ h, const double* __restrict__ acc,
                                const float* __restrict__ gamma, const float* __restrict__ beta,
                                float* __restrict__ out, int M, int do_relu)
{
    int c = threadIdx.x;
    double mean_d = acc[c] / (double)M;
    double var_d = acc[H + c] / (double)M - mean_d * mean_d;
    float mean = (float)mean_d;
    float inv = rsqrtf((float)var_d + 1e-5f);
    float ga = gamma[c], be = beta[c];
    for (int r = blockIdx.x; r < M; r += gridDim.x) {
        size_t i = (size_t)r * H + c;
        float v = fmaf((h[i] - mean) * inv, ga, be);
        if (do_relu) v = fmaxf(v, 0.f);
        out[i] = v;
    }
}

// ---------------- final scatter / pooling / prediction ------------------------
__global__ __launch_bounds__(256) void scatter_kernel(const float* __restrict__ hbn,
                                                      const int* __restrict__ dstg,
                                                      float* __restrict__ node_emb, int Eg)
{
    int c = threadIdx.x;
    int e0 = blockIdx.x * AEPB;
    for (int i = 0; i < AEPB; i++) {
        int e = e0 + i;
        if (e >= Eg) break;
        atomicAdd(node_emb + (size_t)dstg[e] * H + c, hbn[(size_t)e * H + c]);
    }
}

__global__ void pool_kernel(const float* __restrict__ node_emb, const int* __restrict__ batch,
                            float* __restrict__ gsum, float* __restrict__ cnt)
{
    int n = blockIdx.x;
    int c = threadIdx.x;
    int b = batch[n];
    atomicAdd(gsum + (size_t)b * H + c, node_emb[(size_t)n * H + c]);
    if (c == 0) atomicAdd(&cnt[b], 1.0f);
}

__global__ void predict_kernel(const float* __restrict__ gsum, const float* __restrict__ cnt,
                               const float* __restrict__ Wp, const float* __restrict__ bp,
                               float* __restrict__ out)
{
    int g = blockIdx.x, c = threadIdx.x;
    float v = gsum[(size_t)g * H + c] * Wp[c];
    __shared__ float red[8];
#pragma unroll
    for (int o = 16; o > 0; o >>= 1) v += __shfl_down_sync(0xffffffffu, v, o);
    if ((c & 31) == 0) red[c >> 5] = v;
    __syncthreads();
    if (c == 0) {
        float t = 0.f;
#pragma unroll
        for (int i = 0; i < 8; i++) t += red[i];
        out[g] = t / fmaxf(cnt[g], 1.0f) + bp[0];
    }
}

// -------------------------------------------------------------------------------
static void* symA(const void* sym)
{
    void* p = nullptr;
    cudaGetSymbolAddress(&p, sym);
    return p;
}

extern "C" void kernel_launch(void* const* d_in, const int* in_sizes, int n_in,
                              void* d_out, int out_size)
{
    const float* x_g       = (const float*)d_in[0];
    const float* ea_g      = (const float*)d_in[1];
    const float* x_lg      = (const float*)d_in[2];
    const float* edb       = (const float*)d_in[3];
    const float* ea_lg     = (const float*)d_in[4];
    const float* W_enc     = (const float*)d_in[5];
    const float* b_enc     = (const float*)d_in[6];
    const float* W_msg     = (const float*)d_in[7];
    const float* b_msg     = (const float*)d_in[8];
    const float* Wg_nb     = (const float*)d_in[9];
    const float* bg_nb     = (const float*)d_in[10];
    const float* Wg_eb     = (const float*)d_in[11];
    const float* bg_eb     = (const float*)d_in[12];
    const float* Wl_nb     = (const float*)d_in[13];
    const float* bl_nb     = (const float*)d_in[14];
    const float* Wl_eb     = (const float*)d_in[15];
    const float* bl_eb     = (const float*)d_in[16];
    const float* W1        = (const float*)d_in[17];
    const float* b1        = (const float*)d_in[18];
    const float* W2        = (const float*)d_in[19];
    const float* b2        = (const float*)d_in[20];
    const float* bn_gamma  = (const float*)d_in[21];
    const float* bn_beta   = (const float*)d_in[22];
    const float* W_pred    = (const float*)d_in[23];
    const float* b_pred    = (const float*)d_in[24];
    const int*   eig       = (const int*)d_in[25];
    const int*   eil       = (const int*)d_in[26];
    const int*   batch     = (const int*)d_in[27];

    int N   = in_sizes[0] / 16;   // 20000
    int Eg  = in_sizes[1] / 16;   // 200000
    int Elg = in_sizes[4] / 4;    // 400000
    const int L = 4;

    cudaFuncSetAttribute(mma_gemm_kernel, cudaFuncAttributeMaxDynamicSharedMemorySize,
                         GEMM_SMEM);

    float* p_A    = (float*)symA(g_Abuf);
    float* p_B    = (float*)symA(g_Bbuf);
    float* p_h    = (float*)symA(g_h);
    float* p_h2   = (float*)symA(g_h2);
    float* p_m    = (float*)symA(g_m);
    float* p_mmax = (float*)symA(g_mmax);
    float* p_s    = (float*)symA(g_s);
    float* p_w    = (float*)symA(g_w);
    float* p_nbg  = (float*)symA(g_nbg);
    float* p_ebg  = (float*)symA(g_ebg);
    float* p_ne   = (float*)symA(g_nodeemb);
    double* p_bnacc = (double*)symA(g_bnacc);
    float* p_gsum = (float*)symA(g_gsum);
    float* p_cnt  = (float*)symA(g_cnt);

    __nv_bfloat16* p_node_hi = (__nv_bfloat16*)symA(g_node_hi);
    __nv_bfloat16* p_node_lo = (__nv_bfloat16*)symA(g_node_lo);
    __nv_bfloat16* p_act_hi  = (__nv_bfloat16*)symA(g_act_hi);
    __nv_bfloat16* p_act_lo  = (__nv_bfloat16*)symA(g_act_lo);
    __nv_bfloat16* p_hid_hi  = (__nv_bfloat16*)symA(g_hid_hi);
    __nv_bfloat16* p_hid_lo  = (__nv_bfloat16*)symA(g_hid_lo);
    __nv_bfloat16* p_wthi    = (__nv_bfloat16*)symA(g_wthi);
    __nv_bfloat16* p_wtlo    = (__nv_bfloat16*)symA(g_wtlo);

    const int* src_g = eig;
    const int* dst_g = eig + Eg;
    const int* src_l = eil;
    const int* dst_l = eil + Elg;

    int mtE = (Eg + 127) / 128;   // 1563
    int mtN = (N + 127) / 128;    // 157

    // --- weight transpose + split ---
    tsplit_kernel<<<(256 * 256 + 255) / 256, 256>>>(W_msg,           p_wthi + OFF_WA, p_wtlo + OFF_WA, 256, 256);
    tsplit_kernel<<<(256 * 256 + 255) / 256, 256>>>(W_msg + 256 * H, p_wthi + OFF_WB, p_wtlo + OFF_WB, 256, 256);
    for (int l = 0; l < L; l++) {
        tsplit_kernel<<<(256 * 512 + 255) / 256, 256>>>(
            W1 + (size_t)l * 256 * 512, p_wthi + OFF_W1T + l * 131072, p_wtlo + OFF_W1T + l * 131072, 256, 512);
        tsplit_kernel<<<(512 * 256 + 255) / 256, 256>>>(
            W2 + (size_t)l * 512 * 256, p_wthi + OFF_W2T + l * 131072, p_wtlo + OFF_W2T + l * 131072, 512, 256);
    }

    // --- node encoder + msg GEMMs ---
    enc_kernel<<<N, 256>>>(x_g, W_enc, b_enc, p_node_hi, p_node_lo);
    {
        dim3 grid(mtN, 2);
        mma_gemm_kernel<<<grid, 256, GEMM_SMEM>>>(
            p_node_hi, p_node_lo, p_wthi + OFF_WA, p_wtlo + OFF_WA,
            nullptr, nullptr, p_A, nullptr, nullptr, N, 256, 256, 0);
        mma_gemm_kernel<<<grid, 256, GEMM_SMEM>>>(
            p_node_hi, p_node_lo, p_wthi + OFF_WB, p_wtlo + OFF_WB,
            nullptr, nullptr, p_B, nullptr, nullptr, N, 256, 256, 0);
    }
    basis4_kernel<<<(Eg + 255) / 256, 256>>>(edb,   Wg_nb, bg_nb, p_nbg, Eg);
    basis4_kernel<<<(Elg + 255) / 256, 256>>>(ea_lg, Wg_eb, bg_eb, p_ebg, Elg);
    msg_edge_kernel<<<(Eg + MEPB - 1) / MEPB, 256>>>(
        p_A, p_B, ea_g, x_lg, W_msg + 512 * H, W_msg + 528 * H, b_msg,
        src_g, dst_g, p_h, Eg);

    // --- 4 GENConv layers ---
    for (int l = 0; l < L; l++) {
        const float* xptr = p_h;
        if (l > 0) {
            cudaMemsetAsync(p_bnacc, 0, 2 * H * sizeof(double));
            bn_stats_kernel<<<1024, 256>>>(p_h, Eg, p_bnacc);
            bn_apply_kernel<<<2048, 256>>>(p_h, p_bnacc,
                                           bn_gamma + (l - 1) * H, bn_beta + (l - 1) * H,
                                           p_h2, Eg, 1);
            xptr = p_h2;
        }
        cudaMemsetAsync(p_mmax, 0, (size_t)Eg * H * sizeof(float));
        cudaMemsetAsync(p_s,    0, (size_t)Eg * H * sizeof(float));
        cudaMemsetAsync(p_w,    0, (size_t)Eg * H * sizeof(float));
        genA_kernel<<<(Elg + AEPB - 1) / AEPB, 256>>>(
            xptr, p_nbg, p_ebg,
            Wl_nb + l * 4 * H, bl_nb + l * H,
            Wl_eb + l * 4 * H, bl_eb + l * H,
            src_l, dst_l, p_m, p_mmax, Elg);
        genB_kernel<<<(Elg + AEPB - 1) / AEPB, 256>>>(p_m, p_mmax, dst_l, p_s, p_w, Elg);
        genD_kernel<<<Eg, 256>>>(xptr, p_s, p_w, p_act_hi, p_act_lo);

        // GEMM1: hidden = relu(hpre @ W1 + b1), split bf16 out
        {
            dim3 grid(mtE, 4);
            mma_gemm_kernel<<<grid, 256, GEMM_SMEM>>>(
                p_act_hi, p_act_lo, p_wthi + OFF_W1T + l * 131072, p_wtlo + OFF_W1T + l * 131072,
                b1 + l * 512, nullptr, nullptr, p_hid_hi, p_hid_lo,
                Eg, 512, 256, 1 | 2 | 8);
        }
        // GEMM2: h = hidden @ W2 + b2 (+ residual for l>0), fp32 out
        {
            dim3 grid(mtE, 2);
            mma_gemm_kernel<<<grid, 256, GEMM_SMEM>>>(
                p_hid_hi, p_hid_lo, p_wthi + OFF_W2T + l * 131072, p_wtlo + OFF_W2T + l * 131072,
                b2 + l * 256, (l > 0) ? p_h : nullptr, p_h, nullptr, nullptr,
                Eg, 256, 512, (l > 0) ? (1 | 4) : 1);
        }
    }

    // --- final BN (no relu) ---
    cudaMemsetAsync(p_bnacc, 0, 2 * H * sizeof(double));
    bn_stats_kernel<<<1024, 256>>>(p_h, Eg, p_bnacc);
    bn_apply_kernel<<<2048, 256>>>(p_h, p_bnacc, bn_gamma + 3 * H, bn_beta + 3 * H,
                                   p_h2, Eg, 0);

    // --- scatter to nodes, pool per graph, predict ---
    cudaMemsetAsync(p_ne,   0, (size_t)N * H * sizeof(float));
    cudaMemsetAsync(p_gsum, 0, NGRAPH * H * sizeof(float));
    cudaMemsetAsync(p_cnt,  0, NGRAPH * sizeof(float));
    scatter_kernel<<<(Eg + AEPB - 1) / AEPB, 256>>>(p_h2, dst_g, p_ne, Eg);
    pool_kernel<<<N, 256>>>(p_ne, batch, p_gsum, p_cnt);
    predict_kernel<<<NGRAPH, 256>>>(p_gsum, p_cnt, W_pred, b_pred, (float*)d_out);
}

// round 4
// speedup vs baseline: 1.7889x; 1.1598x over previous
#include <cuda_runtime.h>
#include <cuda_bf16.h>
#include <cstdint>

#define H 256
#define NGRAPH 128
#define MAXN   20096
#define MAXEG  200064
#define MAXELG 400128

// ---------------- scratch ----------------
__device__ float g_AB[(size_t)MAXN * 512];
__device__ float g_h[(size_t)MAXEG * H];
__device__ float g_s[(size_t)MAXEG * H];
__device__ float g_w[(size_t)MAXEG * H];
__device__ float g_nbg[(size_t)MAXEG * 4];
__device__ float g_ebg[(size_t)MAXELG * 4];
__device__ float g_nodeemb[(size_t)MAXN * H];
__device__ double g_bnacc[2 * H];
__device__ float g_bnscale[H];
__device__ float g_bnshift[H];
__device__ float g_gsum[NGRAPH * H];
__device__ float g_cnt[NGRAPH];

// bf16 split buffers (padded to tile multiples; contents always finite)
__device__ __nv_bfloat16 g_node_hi[(size_t)MAXN * H];
__device__ __nv_bfloat16 g_node_lo[(size_t)MAXN * H];
__device__ __nv_bfloat16 g_act_hi[(size_t)MAXEG * H];
__device__ __nv_bfloat16 g_act_lo[(size_t)MAXEG * H];
__device__ __nv_bfloat16 g_hid_hi[(size_t)MAXEG * 2 * H];
__device__ __nv_bfloat16 g_hid_lo[(size_t)MAXEG * 2 * H];

// transposed/split weights arena (elements)
#define OFF_WMSG 0
#define OFF_W1T  (512 * 256)
#define OFF_W2T  (OFF_W1T + 4 * 131072)
#define WT_TOTAL (OFF_W2T + 4 * 131072)
__device__ __nv_bfloat16 g_wthi[WT_TOTAL];
__device__ __nv_bfloat16 g_wtlo[WT_TOTAL];

// ======================= helpers =======================
__device__ __forceinline__ uint32_t smem_u32(const void* p) {
    uint32_t a;
    asm("{ .reg .u64 t; cvta.to.shared.u64 t, %1; cvt.u32.u64 %0, t; }" : "=r"(a) : "l"(p));
    return a;
}
#define CP16(dst, src) \
    asm volatile("cp.async.cg.shared.global [%0], [%1], 16;" :: "r"(dst), "l"(src) : "memory")
#define CP_COMMIT() asm volatile("cp.async.commit_group;" ::: "memory")
#define CP_WAIT2()  asm volatile("cp.async.wait_group 2;" ::: "memory")

__device__ __forceinline__ void ldm4(uint32_t (&r)[4], uint32_t addr) {
    asm volatile("ldmatrix.sync.aligned.m8n8.x4.shared.b16 {%0,%1,%2,%3}, [%4];"
                 : "=r"(r[0]), "=r"(r[1]), "=r"(r[2]), "=r"(r[3]) : "r"(addr));
}
__device__ __forceinline__ void mma_bf16(float (&d)[4], const uint32_t (&a)[4], const uint32_t* b) {
    asm volatile(
        "mma.sync.aligned.m16n8k16.row.col.f32.bf16.bf16.f32 "
        "{%0,%1,%2,%3}, {%4,%5,%6,%7}, {%8,%9}, {%0,%1,%2,%3};"
        : "+f"(d[0]), "+f"(d[1]), "+f"(d[2]), "+f"(d[3])
        : "r"(a[0]), "r"(a[1]), "r"(a[2]), "r"(a[3]), "r"(b[0]), "r"(b[1]));
}
__device__ __forceinline__ void split2(float v, __nv_bfloat16& hi, __nv_bfloat16& lo) {
    hi = __float2bfloat16(v);
    lo = __float2bfloat16(v - __bfloat162float(hi));
}

// ======================= mma.sync split-bf16 GEMM =======================
// C[M,N] = A[M,K] @ W[K,N]; A as (Ahi,Alo) bf16 [M,K] row-major,
// W transposed as (Bhi,Blo) bf16 [N,K] row-major.
// flags: 1=bias, 2=relu, 4=residual(fp32 [M,N]), 8=split-out bf16 (else fp32 out)
#define RB 80
#define TILE_B (128 * RB)
#define SO_AHI 0
#define SO_ALO (1 * TILE_B)
#define SO_BHI (2 * TILE_B)
#define SO_BLO (3 * TILE_B)
#define STAGE_B (4 * TILE_B)
#define NSTAGE 4
#define GEMM_SMEM (NSTAGE * STAGE_B)

__device__ __forceinline__ void load_stage(uint32_t sbase,
    const __nv_bfloat16* __restrict__ A_hi, const __nv_bfloat16* __restrict__ A_lo,
    const __nv_bfloat16* __restrict__ B_hi, const __nv_bfloat16* __restrict__ B_lo,
    int K, int m0, int n0, int k0, int tid)
{
#pragma unroll
    for (int i = 0; i < 2; i++) {
        int g = tid + i * 256;
        int row = g >> 2, ch = g & 3;
        uint32_t so = (uint32_t)row * RB + (uint32_t)ch * 16;
        size_t ao = (size_t)(m0 + row) * K + k0 + ch * 8;
        size_t bo = (size_t)(n0 + row) * K + k0 + ch * 8;
        CP16(sbase + SO_AHI + so, A_hi + ao);
        CP16(sbase + SO_ALO + so, A_lo + ao);
        CP16(sbase + SO_BHI + so, B_hi + bo);
        CP16(sbase + SO_BLO + so, B_lo + bo);
    }
}

__device__ __forceinline__ void load_frags(uint32_t base, int kk8,
    int a_row, int a_k8, int b_row, int b_k8, int no,
    uint32_t (&ah)[2][4], uint32_t (&al)[2][4],
    uint32_t (&bh)[4][4], uint32_t (&bl)[4][4])
{
#pragma unroll
    for (int i = 0; i < 2; i++) {
        uint32_t aaddr = base + SO_AHI + (uint32_t)(a_row + i * 16) * RB
                       + (uint32_t)(kk8 + a_k8) * 16;
        ldm4(ah[i], aaddr);
        ldm4(al[i], aaddr + (SO_ALO - SO_AHI));
    }
#pragma unroll
    for (int j = 0; j < 4; j++) {
        uint32_t baddr = base + SO_BHI + (uint32_t)(no + j * 16 + b_row) * RB
                       + (uint32_t)(kk8 + b_k8) * 16;
        ldm4(bh[j], baddr);
        ldm4(bl[j], baddr + (SO_BLO - SO_BHI));
    }
}

__device__ __forceinline__ void mma_block(float (&acc)[2][8][4],
    const uint32_t (&ah)[2][4], const uint32_t (&al)[2][4],
    const uint32_t (&bh)[4][4], const uint32_t (&bl)[4][4])
{
#pragma unroll
    for (int i = 0; i < 2; i++)
#pragma unroll
        for (int j = 0; j < 4; j++) {
            mma_bf16(acc[i][2 * j],     ah[i], &bh[j][0]);
            mma_bf16(acc[i][2 * j + 1], ah[i], &bh[j][2]);
            mma_bf16(acc[i][2 * j],     ah[i], &bl[j][0]);
            mma_bf16(acc[i][2 * j + 1], ah[i], &bl[j][2]);
            mma_bf16(acc[i][2 * j],     al[i], &bh[j][0]);
            mma_bf16(acc[i][2 * j + 1], al[i], &bh[j][2]);
        }
}

__global__ __launch_bounds__(256, 1) void mma_gemm_kernel(
    const __nv_bfloat16* __restrict__ Ahi, const __nv_bfloat16* __restrict__ Alo,
    const __nv_bfloat16* __restrict__ Bhi, const __nv_bfloat16* __restrict__ Blo,
    const float* __restrict__ bias, const float* __restrict__ res,
    float* __restrict__ Cf, __nv_bfloat16* __restrict__ Chi, __nv_bfloat16* __restrict__ Clo,
    int M, int N, int K, int flags)
{
    extern __shared__ __align__(128) char smem[];
    uint32_t sb = smem_u32(smem);
    int tid = threadIdx.x;
    int wid = tid >> 5, lane = tid & 31;
    int m0 = blockIdx.x * 128, n0 = blockIdx.y * 128;
    int nk = K >> 5;

#pragma unroll
    for (int s = 0; s < 3; s++) {
        load_stage(sb + s * STAGE_B, Ahi, Alo, Bhi, Blo, K, m0, n0, s * 32, tid);
        CP_COMMIT();
    }

    float acc[2][8][4];
#pragma unroll
    for (int i = 0; i < 2; i++)
#pragma unroll
        for (int j = 0; j < 8; j++)
#pragma unroll
            for (int q = 0; q < 4; q++) acc[i][j][q] = 0.f;

    int mo = (wid >> 1) * 32, no = (wid & 1) * 64;
    int a_row = mo + (lane & 15);
    int a_k8  = lane >> 4;
    int b_row = ((lane >> 4) << 3) + (lane & 7);
    int b_k8  = (lane >> 3) & 1;

    uint32_t ah0[2][4], al0[2][4], bh0[4][4], bl0[4][4];
    uint32_t ah1[2][4], al1[2][4], bh1[4][4], bl1[4][4];

    for (int k = 0; k < nk; k++) {
        CP_WAIT2();
        __syncthreads();
        uint32_t base = sb + (uint32_t)(k & 3) * STAGE_B;
        int kn = k + 3;
        if (kn < nk)
            load_stage(sb + (uint32_t)(kn & 3) * STAGE_B, Ahi, Alo, Bhi, Blo,
                       K, m0, n0, kn * 32, tid);
        CP_COMMIT();
        load_frags(base, 0, a_row, a_k8, b_row, b_k8, no, ah0, al0, bh0, bl0);
        load_frags(base, 2, a_row, a_k8, b_row, b_k8, no, ah1, al1, bh1, bl1);
        mma_block(acc, ah0, al0, bh0, bl0);
        mma_block(acc, ah1, al1, bh1, bl1);
    }

    // epilogue
#pragma unroll
    for (int i = 0; i < 2; i++) {
        int r0 = m0 + mo + i * 16 + (lane >> 2);
#pragma unroll
        for (int half = 0; half < 2; half++) {
            int r = r0 + half * 8;
            if (r >= M) continue;
#pragma unroll
            for (int nb = 0; nb < 8; nb++) {
                int col = n0 + no + nb * 8 + 2 * (lane & 3);
                float v0 = acc[i][nb][half * 2 + 0];
                float v1 = acc[i][nb][half * 2 + 1];
                if (flags & 1) { v0 += bias[col]; v1 += bias[col + 1]; }
                if (flags & 4) {
                    float2 t = *(const float2*)(res + (size_t)r * N + col);
                    v0 += t.x; v1 += t.y;
                }
                if (flags & 2) { v0 = fmaxf(v0, 0.f); v1 = fmaxf(v1, 0.f); }
                if (flags & 8) {
                    __nv_bfloat16 h0, l0, h1, l1;
                    split2(v0, h0, l0);
                    split2(v1, h1, l1);
                    *(__nv_bfloat162*)(Chi + (size_t)r * N + col) = __halves2bfloat162(h0, h1);
                    *(__nv_bfloat162*)(Clo + (size_t)r * N + col) = __halves2bfloat162(l0, l1);
                } else {
                    *(float2*)(Cf + (size_t)r * N + col) = make_float2(v0, v1);
                }
            }
        }
    }
}

// ---------------- weight transpose+split: W[K,N] -> T[N,K] hi/lo --------------
__global__ void tsplit_kernel(const float* __restrict__ W,
                              __nv_bfloat16* __restrict__ thi, __nv_bfloat16* __restrict__ tlo,
                              int K, int N)
{
    int idx = blockIdx.x * 256 + threadIdx.x;
    if (idx >= K * N) return;
    int k = idx / N, n = idx % N;
    __nv_bfloat16 hi, lo;
    split2(W[idx], hi, lo);
    thi[(size_t)n * K + k] = hi;
    tlo[(size_t)n * K + k] = lo;
}

// ---------------- node encoder -------------------------------------------------
__global__ void enc_kernel(const float* __restrict__ xg, const float* __restrict__ W,
                           const float* __restrict__ b,
                           __nv_bfloat16* __restrict__ hi, __nv_bfloat16* __restrict__ lo)
{
    __shared__ float sx[16];
    int n = blockIdx.x, c = threadIdx.x;
    if (c < 16) sx[c] = xg[(size_t)n * 16 + c];
    __syncthreads();
    float v = b[c];
#pragma unroll
    for (int k = 0; k < 16; k++) v = fmaf(sx[k], W[k * H + c], v);
    __nv_bfloat16 h, l;
    split2(v, h, l);
    hi[(size_t)n * H + c] = h;
    lo[(size_t)n * H + c] = l;
}

// ---------------- tiny [E,4]@[4,4]+b projection -------------------------------
__global__ void basis4_kernel(const float* __restrict__ in, const float* __restrict__ W,
                              const float* __restrict__ b, float* __restrict__ out, int E)
{
    int e = blockIdx.x * blockDim.x + threadIdx.x;
    if (e >= E) return;
    float4 x = *(const float4*)(in + (size_t)e * 4);
    float o0 = b[0] + x.x * W[0] + x.y * W[4] + x.z * W[8]  + x.w * W[12];
    float o1 = b[1] + x.x * W[1] + x.y * W[5] + x.z * W[9]  + x.w * W[13];
    float o2 = b[2] + x.x * W[2] + x.y * W[6] + x.z * W[10] + x.w * W[14];
    float o3 = b[3] + x.x * W[3] + x.y * W[7] + x.z * W[11] + x.w * W[15];
    *(float4*)(out + (size_t)e * 4) = make_float4(o0, o1, o2, o3);
}

// ---------------- fused first-message (AB combined buffer, stride 512) --------
#define MEPB 16
__global__ __launch_bounds__(256) void msg_edge_kernel(
    const float* __restrict__ AB,
    const float* __restrict__ ea, const float* __restrict__ xlg,
    const float* __restrict__ Wc, const float* __restrict__ Wd,
    const float* __restrict__ bmsg,
    const int* __restrict__ srcg, const int* __restrict__ dstg,
    float* __restrict__ h, int Eg)
{
    __shared__ float sWc[16 * H];
    __shared__ float sWd[4 * H];
    __shared__ float sb[H];
    __shared__ float sea[MEPB][16];
    __shared__ float sxl[MEPB][4];
    int tid = threadIdx.x;
    for (int i = tid; i < 16 * H; i += 256) sWc[i] = Wc[i];
    for (int i = tid; i < 4 * H; i += 256) sWd[i] = Wd[i];
    sb[tid] = bmsg[tid];
    int e0 = blockIdx.x * MEPB;
    for (int i = tid; i < MEPB * 16; i += 256) {
        int e = e0 + i / 16;
        if (e < Eg) sea[i / 16][i % 16] = ea[(size_t)e * 16 + (i % 16)];
    }
    for (int i = tid; i < MEPB * 4; i += 256) {
        int e = e0 + i / 4;
        if (e < Eg) sxl[i / 4][i % 4] = xlg[(size_t)e * 4 + (i % 4)];
    }
    __syncthreads();
    int c = tid;
    for (int i = 0; i < MEPB; i++) {
        int e = e0 + i;
        if (e >= Eg) break;
        int s = srcg[e], d = dstg[e];
        float v = AB[(size_t)s * 512 + c] + AB[(size_t)d * 512 + 256 + c] + sb[c];
#pragma unroll
        for (int k = 0; k < 16; k++) v = fmaf(sea[i][k], sWc[k * H + c], v);
#pragma unroll
        for (int k = 0; k < 4; k++) v = fmaf(sxl[i][k], sWd[k * H + c], v);
        h[(size_t)e * H + c] = v;
    }
}

// ---------------- BN coefficient computation ----------------------------------
__global__ void bn_coef_kernel(const double* __restrict__ acc,
                               const float* __restrict__ gamma, const float* __restrict__ beta,
                               float* __restrict__ scale, float* __restrict__ shift, int M)
{
    int c = threadIdx.x;
    double mu = acc[c] / (double)M;
    double var = acc[H + c] / (double)M - mu * mu;
    float inv = rsqrtf((float)var + 1e-5f);
    float sc = gamma[c] * inv;
    scale[c] = sc;
    shift[c] = beta[c] - (float)mu * sc;
}

// ---------------- fused GENConv aggregation -----------------------------------
// m = relu(BN?(x[src]) + nb(src) + eb(e)) + eps; s += exp(m); w += exp(m)*m
#define AEPB 8
__global__ __launch_bounds__(256) void genAB_kernel(
    const float* __restrict__ x, const float* __restrict__ nbg, const float* __restrict__ ebg,
    const float* __restrict__ Wnb, const float* __restrict__ bnb,
    const float* __restrict__ Web, const float* __restrict__ beb,
    const float* __restrict__ bnscale, const float* __restrict__ bnshift,
    const int* __restrict__ src, const int* __restrict__ dst,
    float* __restrict__ svec, float* __restrict__ wvec, int Elg, int use_bn)
{
    __shared__ float sWn[4 * H], sWe[4 * H], sbn[H], sbe[H];
    int tid = threadIdx.x;
    for (int i = tid; i < 4 * H; i += 256) { sWn[i] = Wnb[i]; sWe[i] = Web[i]; }
    sbn[tid] = bnb[tid];
    sbe[tid] = beb[tid];
    __syncthreads();
    int c = tid;
    float sc = 1.f, sh = 0.f;
    if (use_bn) { sc = bnscale[c]; sh = bnshift[c]; }
    int e0 = blockIdx.x * AEPB;
    for (int i = 0; i < AEPB; i++) {
        int e = e0 + i;
        if (e >= Elg) break;
        int s = src[e], d = dst[e];
        float4 nv = *(const float4*)(nbg + (size_t)s * 4);
        float4 ev4 = *(const float4*)(ebg + (size_t)e * 4);
        float nbv = sbn[c];
        nbv = fmaf(nv.x, sWn[c], nbv);
        nbv = fmaf(nv.y, sWn[H + c], nbv);
        nbv = fmaf(nv.z, sWn[2 * H + c], nbv);
        nbv = fmaf(nv.w, sWn[3 * H + c], nbv);
        float ebv = sbe[c];
        ebv = fmaf(ev4.x, sWe[c], ebv);
        ebv = fmaf(ev4.y, sWe[H + c], ebv);
        ebv = fmaf(ev4.z, sWe[2 * H + c], ebv);
        ebv = fmaf(ev4.w, sWe[3 * H + c], ebv);
        float xv = x[(size_t)s * H + c];
        if (use_bn) xv = fmaxf(fmaf(xv, sc, sh), 0.f);
        float mv = fmaxf(xv + nbv + ebv, 0.f) + 1e-7f;
        float ev = expf(fminf(mv, 80.f));
        atomicAdd(svec + (size_t)d * H + c, ev);
        atomicAdd(wvec + (size_t)d * H + c, ev * mv);
    }
}

// ---------------- GENConv combine: hpre = BN?(x) + w/(s+eps) -> split bf16 ----
__global__ void genD_kernel(const float* __restrict__ x, const float* __restrict__ svec,
                            const float* __restrict__ wvec,
                            const float* __restrict__ bnscale, const float* __restrict__ bnshift,
                            __nv_bfloat16* __restrict__ ahi, __nv_bfloat16* __restrict__ alo,
                            int use_bn)
{
    int c = threadIdx.x;
    size_t i = (size_t)blockIdx.x * H + c;
    float xv = x[i];
    if (use_bn) xv = fmaxf(fmaf(xv, bnscale[c], bnshift[c]), 0.f);
    float v = xv + wvec[i] / (svec[i] + 1e-16f);
    __nv_bfloat16 h, l;
    split2(v, h, l);
    ahi[i] = h;
    alo[i] = l;
}

// ---------------- BatchNorm statistics ----------------------------------------
__global__ void bn_stats_kernel(const float* __restrict__ h, int M, double* __restrict__ acc)
{
    int c = threadIdx.x;
    float s = 0.f, s2 = 0.f;
    for (int r = blockIdx.x; r < M; r += gridDim.x) {
        float v = h[(size_t)r * H + c];
        s += v;
        s2 = fmaf(v, v, s2);
    }
    atomicAdd(&acc[c], (double)s);
    atomicAdd(&acc[H + c], (double)s2);
}

// ---------------- final scatter (BN fused) / pooling / prediction -------------
__global__ __launch_bounds__(256) void scatter_bn_kernel(
    const float* __restrict__ h, const float* __restrict__ bnscale,
    const float* __restrict__ bnshift, const int* __restrict__ dstg,
    float* __restrict__ node_emb, int Eg)
{
    int c = threadIdx.x;
    float sc = bnscale[c], sh = bnshift[c];
    int e0 = blockIdx.x * AEPB;
    for (int i = 0; i < AEPB; i++) {
        int e = e0 + i;
        if (e >= Eg) break;
        float v = fmaf(h[(size_t)e * H + c], sc, sh);
        atomicAdd(node_emb + (size_t)dstg[e] * H + c, v);
    }
}

__global__ void pool_kernel(const float* __restrict__ node_emb, const int* __restrict__ batch,
                            float* __restrict__ gsum, float* __restrict__ cnt)
{
    int n = blockIdx.x;
    int c = threadIdx.x;
    int b = batch[n];
    atomicAdd(gsum + (size_t)b * H + c, node_emb[(size_t)n * H + c]);
    if (c == 0) atomicAdd(&cnt[b], 1.0f);
}

__global__ void predict_kernel(const float* __restrict__ gsum, const float* __restrict__ cnt,
                               const float* __restrict__ Wp, const float* __restrict__ bp,
                               float* __restrict__ out)
{
    int g = blockIdx.x, c = threadIdx.x;
    float v = gsum[(size_t)g * H + c] * Wp[c];
    __shared__ float red[8];
#pragma unroll
    for (int o = 16; o > 0; o >>= 1) v += __shfl_down_sync(0xffffffffu, v, o);
    if ((c & 31) == 0) red[c >> 5] = v;
    __syncthreads();
    if (c == 0) {
        float t = 0.f;
#pragma unroll
        for (int i = 0; i < 8; i++) t += red[i];
        out[g] = t / fmaxf(cnt[g], 1.0f) + bp[0];
    }
}

// -------------------------------------------------------------------------------
static void* symA(const void* sym)
{
    void* p = nullptr;
    cudaGetSymbolAddress(&p, sym);
    return p;
}

extern "C" void kernel_launch(void* const* d_in, const int* in_sizes, int n_in,
                              void* d_out, int out_size)
{
    const float* x_g       = (const float*)d_in[0];
    const float* ea_g      = (const float*)d_in[1];
    const float* x_lg      = (const float*)d_in[2];
    const float* edb       = (const float*)d_in[3];
    const float* ea_lg     = (const float*)d_in[4];
    const float* W_enc     = (const float*)d_in[5];
    const float* b_enc     = (const float*)d_in[6];
    const float* W_msg     = (const float*)d_in[7];
    const float* b_msg     = (const float*)d_in[8];
    const float* Wg_nb     = (const float*)d_in[9];
    const float* bg_nb     = (const float*)d_in[10];
    const float* Wg_eb     = (const float*)d_in[11];
    const float* bg_eb     = (const float*)d_in[12];
    const float* Wl_nb     = (const float*)d_in[13];
    const float* bl_nb     = (const float*)d_in[14];
    const float* Wl_eb     = (const float*)d_in[15];
    const float* bl_eb     = (const float*)d_in[16];
    const float* W1        = (const float*)d_in[17];
    const float* b1        = (const float*)d_in[18];
    const float* W2        = (const float*)d_in[19];
    const float* b2        = (const float*)d_in[20];
    const float* bn_gamma  = (const float*)d_in[21];
    const float* bn_beta   = (const float*)d_in[22];
    const float* W_pred    = (const float*)d_in[23];
    const float* b_pred    = (const float*)d_in[24];
    const int*   eig       = (const int*)d_in[25];
    const int*   eil       = (const int*)d_in[26];
    const int*   batch     = (const int*)d_in[27];

    int N   = in_sizes[0] / 16;   // 20000
    int Eg  = in_sizes[1] / 16;   // 200000
    int Elg = in_sizes[4] / 4;    // 400000
    const int L = 4;

    cudaFuncSetAttribute(mma_gemm_kernel, cudaFuncAttributeMaxDynamicSharedMemorySize,
                         GEMM_SMEM);

    float* p_AB   = (float*)symA(g_AB);
    float* p_h    = (float*)symA(g_h);
    float* p_s    = (float*)symA(g_s);
    float* p_w    = (float*)symA(g_w);
    float* p_nbg  = (float*)symA(g_nbg);
    float* p_ebg  = (float*)symA(g_ebg);
    float* p_ne   = (float*)symA(g_nodeemb);
    double* p_bnacc = (double*)symA(g_bnacc);
    float* p_bnsc = (float*)symA(g_bnscale);
    float* p_bnsh = (float*)symA(g_bnshift);
    float* p_gsum = (float*)symA(g_gsum);
    float* p_cnt  = (float*)symA(g_cnt);

    __nv_bfloat16* p_node_hi = (__nv_bfloat16*)symA(g_node_hi);
    __nv_bfloat16* p_node_lo = (__nv_bfloat16*)symA(g_node_lo);
    __nv_bfloat16* p_act_hi  = (__nv_bfloat16*)symA(g_act_hi);
    __nv_bfloat16* p_act_lo  = (__nv_bfloat16*)symA(g_act_lo);
    __nv_bfloat16* p_hid_hi  = (__nv_bfloat16*)symA(g_hid_hi);
    __nv_bfloat16* p_hid_lo  = (__nv_bfloat16*)symA(g_hid_lo);
    __nv_bfloat16* p_wthi    = (__nv_bfloat16*)symA(g_wthi);
    __nv_bfloat16* p_wtlo    = (__nv_bfloat16*)symA(g_wtlo);

    const int* src_g = eig;
    const int* dst_g = eig + Eg;
    const int* src_l = eil;
    const int* dst_l = eil + Elg;

    int mtE = (Eg + 127) / 128;   // 1563
    int mtN = (N + 127) / 128;    // 157

    // --- weight transpose + split ---
    tsplit_kernel<<<(65536 + 255) / 256, 256>>>(W_msg,           p_wthi + OFF_WMSG,         p_wtlo + OFF_WMSG,         256, 256);
    tsplit_kernel<<<(65536 + 255) / 256, 256>>>(W_msg + 256 * H, p_wthi + OFF_WMSG + 65536, p_wtlo + OFF_WMSG + 65536, 256, 256);
    for (int l = 0; l < L; l++) {
        tsplit_kernel<<<(131072 + 255) / 256, 256>>>(
            W1 + (size_t)l * 131072, p_wthi + OFF_W1T + l * 131072, p_wtlo + OFF_W1T + l * 131072, 256, 512);
        tsplit_kernel<<<(131072 + 255) / 256, 256>>>(
            W2 + (size_t)l * 131072, p_wthi + OFF_W2T + l * 131072, p_wtlo + OFF_W2T + l * 131072, 512, 256);
    }

    // --- node encoder + combined msg GEMM (N=512) ---
    enc_kernel<<<N, 256>>>(x_g, W_enc, b_enc, p_node_hi, p_node_lo);
    {
        dim3 grid(mtN, 4);
        mma_gemm_kernel<<<grid, 256, GEMM_SMEM>>>(
            p_node_hi, p_node_lo, p_wthi + OFF_WMSG, p_wtlo + OFF_WMSG,
            nullptr, nullptr, p_AB, nullptr, nullptr, N, 512, 256, 0);
    }
    basis4_kernel<<<(Eg + 255) / 256, 256>>>(edb,   Wg_nb, bg_nb, p_nbg, Eg);
    basis4_kernel<<<(Elg + 255) / 256, 256>>>(ea_lg, Wg_eb, bg_eb, p_ebg, Elg);
    msg_edge_kernel<<<(Eg + MEPB - 1) / MEPB, 256>>>(
        p_AB, ea_g, x_lg, W_msg + 512 * H, W_msg + 528 * H, b_msg,
        src_g, dst_g, p_h, Eg);

    // --- 4 GENConv layers ---
    for (int l = 0; l < L; l++) {
        int use_bn = (l > 0) ? 1 : 0;
        if (use_bn) {
            cudaMemsetAsync(p_bnacc, 0, 2 * H * sizeof(double));
            bn_stats_kernel<<<1024, 256>>>(p_h, Eg, p_bnacc);
            bn_coef_kernel<<<1, 256>>>(p_bnacc, bn_gamma + (l - 1) * H, bn_beta + (l - 1) * H,
                                       p_bnsc, p_bnsh, Eg);
        }
        cudaMemsetAsync(p_s, 0, (size_t)Eg * H * sizeof(float));
        cudaMemsetAsync(p_w, 0, (size_t)Eg * H * sizeof(float));
        genAB_kernel<<<(Elg + AEPB - 1) / AEPB, 256>>>(
            p_h, p_nbg, p_ebg,
            Wl_nb + l * 4 * H, bl_nb + l * H,
            Wl_eb + l * 4 * H, bl_eb + l * H,
            p_bnsc, p_bnsh, src_l, dst_l, p_s, p_w, Elg, use_bn);
        genD_kernel<<<Eg, 256>>>(p_h, p_s, p_w, p_bnsc, p_bnsh, p_act_hi, p_act_lo, use_bn);

        // GEMM1: hidden = relu(hpre @ W1 + b1), split bf16 out
        {
            dim3 grid(mtE, 4);
            mma_gemm_kernel<<<grid, 256, GEMM_SMEM>>>(
                p_act_hi, p_act_lo, p_wthi + OFF_W1T + l * 131072, p_wtlo + OFF_W1T + l * 131072,
                b1 + l * 512, nullptr, nullptr, p_hid_hi, p_hid_lo,
                Eg, 512, 256, 1 | 2 | 8);
        }
        // GEMM2: h = hidden @ W2 + b2 (+ residual for l>0), fp32 out
        {
            dim3 grid(mtE, 2);
            mma_gemm_kernel<<<grid, 256, GEMM_SMEM>>>(
                p_hid_hi, p_hid_lo, p_wthi + OFF_W2T + l * 131072, p_wtlo + OFF_W2T + l * 131072,
                b2 + l * 256, (l > 0) ? p_h : nullptr, p_h, nullptr, nullptr,
                Eg, 256, 512, (l > 0) ? (1 | 4) : 1);
        }
    }

    // --- final BN coefs + fused scatter ---
    cudaMemsetAsync(p_bnacc, 0, 2 * H * sizeof(double));
    bn_stats_kernel<<<1024, 256>>>(p_h, Eg, p_bnacc);
    bn_coef_kernel<<<1, 256>>>(p_bnacc, bn_gamma + 3 * H, bn_beta + 3 * H, p_bnsc, p_bnsh, Eg);

    cudaMemsetAsync(p_ne,   0, (size_t)N * H * sizeof(float));
    cudaMemsetAsync(p_gsum, 0, NGRAPH * H * sizeof(float));
    cudaMemsetAsync(p_cnt,  0, NGRAPH * sizeof(float));
    scatter_bn_kernel<<<(Eg + AEPB - 1) / AEPB, 256>>>(p_h, p_bnsc, p_bnsh, dst_g, p_ne, Eg);
    pool_kernel<<<N, 256>>>(p_ne, batch, p_gsum, p_cnt);
    predict_kernel<<<NGRAPH, 256>>>(p_gsum, p_cnt, W_pred, b_pred, (float*)d_out);
}

// round 5
// speedup vs baseline: 1.8337x; 1.0250x over previous
#include <cuda_runtime.h>
#include <cuda_bf16.h>
#include <cstdint>

#define H 256
#define NGRAPH 128
#define MAXN   20224
#define MAXEG  200192
#define MAXELG 400128

// ---------------- scratch ----------------
__device__ float g_AB[(size_t)MAXN * 512];
__device__ float g_h[(size_t)MAXEG * H];
__device__ float g_s[(size_t)MAXEG * H];
__device__ float g_w[(size_t)MAXEG * H];
__device__ float g_nbg[(size_t)MAXEG * 4];
__device__ float g_ebg[(size_t)MAXELG * 4];
__device__ float g_nodeemb[(size_t)MAXN * H];
__device__ double g_bnacc[2 * H];
__device__ float g_bnscale[H];
__device__ float g_bnshift[H];
__device__ float g_gsum[NGRAPH * H];
__device__ float g_cnt[NGRAPH];

// bf16 split buffers (padded to 256-row tiles; pad rows stay zero => finite)
__device__ __nv_bfloat16 g_node_hi[(size_t)MAXN * H];
__device__ __nv_bfloat16 g_node_lo[(size_t)MAXN * H];
__device__ __nv_bfloat16 g_act_hi[(size_t)MAXEG * H];
__device__ __nv_bfloat16 g_act_lo[(size_t)MAXEG * H];
__device__ __nv_bfloat16 g_hid_hi[(size_t)MAXEG * 2 * H];
__device__ __nv_bfloat16 g_hid_lo[(size_t)MAXEG * 2 * H];

// transposed/split weights arena (elements)
#define OFF_WMSG 0
#define OFF_W1T  (512 * 256)
#define OFF_W2T  (OFF_W1T + 4 * 131072)
#define WT_TOTAL (OFF_W2T + 4 * 131072)
__device__ __nv_bfloat16 g_wthi[WT_TOTAL];
__device__ __nv_bfloat16 g_wtlo[WT_TOTAL];

// ======================= helpers =======================
__device__ __forceinline__ uint32_t smem_u32(const void* p) {
    uint32_t a;
    asm("{ .reg .u64 t; cvta.to.shared.u64 t, %1; cvt.u32.u64 %0, t; }" : "=r"(a) : "l"(p));
    return a;
}
#define CP16(dst, src) \
    asm volatile("cp.async.cg.shared.global [%0], [%1], 16;" :: "r"(dst), "l"(src) : "memory")
#define CP_COMMIT() asm volatile("cp.async.commit_group;" ::: "memory")
#define CP_WAIT1()  asm volatile("cp.async.wait_group 1;" ::: "memory")
#define CP_WAIT0()  asm volatile("cp.async.wait_group 0;" ::: "memory")

__device__ __forceinline__ void ldm4(uint32_t (&r)[4], uint32_t addr) {
    asm volatile("ldmatrix.sync.aligned.m8n8.x4.shared.b16 {%0,%1,%2,%3}, [%4];"
                 : "=r"(r[0]), "=r"(r[1]), "=r"(r[2]), "=r"(r[3]) : "r"(addr));
}
__device__ __forceinline__ void mma_bf16(float (&d)[4], const uint32_t (&a)[4], const uint32_t* b) {
    asm volatile(
        "mma.sync.aligned.m16n8k16.row.col.f32.bf16.bf16.f32 "
        "{%0,%1,%2,%3}, {%4,%5,%6,%7}, {%8,%9}, {%0,%1,%2,%3};"
        : "+f"(d[0]), "+f"(d[1]), "+f"(d[2]), "+f"(d[3])
        : "r"(a[0]), "r"(a[1]), "r"(a[2]), "r"(a[3]), "r"(b[0]), "r"(b[1]));
}
__device__ __forceinline__ void split2(float v, __nv_bfloat16& hi, __nv_bfloat16& lo) {
    hi = __float2bfloat16(v);
    lo = __float2bfloat16(v - __bfloat162float(hi));
}

// ======================= mma.sync split-bf16 GEMM =======================
// C[M,N] = A[M,K] @ W[K,N]; A as (Ahi,Alo) bf16 [M,K] row-major,
// W transposed as (Bhi,Blo) bf16 [N,K] row-major.
// CTA tile 256x128, 8 warps of 64x64, BK=32, 3 stages.
// flags: 1=bias, 2=relu, 4=residual(fp32 [M,N]), 8=split-out bf16 (else fp32 out)
#define RB 80
#define A_TILE_B (256 * RB)        // 20480
#define B_TILE_B (128 * RB)        // 10240
#define SO_AHI 0
#define SO_ALO A_TILE_B
#define SO_BHI (2 * A_TILE_B)
#define SO_BLO (2 * A_TILE_B + B_TILE_B)
#define STAGE_B (2 * A_TILE_B + 2 * B_TILE_B)   // 61440
#define NSTAGE 3
#define GEMM_SMEM (NSTAGE * STAGE_B)            // 184320

__device__ __forceinline__ void load_stage(uint32_t sbase,
    const __nv_bfloat16* __restrict__ A_hi, const __nv_bfloat16* __restrict__ A_lo,
    const __nv_bfloat16* __restrict__ B_hi, const __nv_bfloat16* __restrict__ B_lo,
    int K, int m0, int n0, int k0, int tid)
{
#pragma unroll
    for (int i = 0; i < 4; i++) {              // A: 256 rows x 4 chunks
        int g = tid + i * 256;
        int row = g >> 2, ch = g & 3;
        uint32_t so = (uint32_t)row * RB + (uint32_t)ch * 16;
        size_t ao = (size_t)(m0 + row) * K + k0 + ch * 8;
        CP16(sbase + SO_AHI + so, A_hi + ao);
        CP16(sbase + SO_ALO + so, A_lo + ao);
    }
#pragma unroll
    for (int i = 0; i < 2; i++) {              // B: 128 rows x 4 chunks
        int g = tid + i * 256;
        int row = g >> 2, ch = g & 3;
        uint32_t so = (uint32_t)row * RB + (uint32_t)ch * 16;
        size_t bo = (size_t)(n0 + row) * K + k0 + ch * 8;
        CP16(sbase + SO_BHI + so, B_hi + bo);
        CP16(sbase + SO_BLO + so, B_lo + bo);
    }
}

__global__ __launch_bounds__(256, 1) void mma_gemm_kernel(
    const __nv_bfloat16* __restrict__ Ahi, const __nv_bfloat16* __restrict__ Alo,
    const __nv_bfloat16* __restrict__ Bhi, const __nv_bfloat16* __restrict__ Blo,
    const float* __restrict__ bias, const float* __restrict__ res,
    float* __restrict__ Cf, __nv_bfloat16* __restrict__ Chi, __nv_bfloat16* __restrict__ Clo,
    int M, int N, int K, int flags)
{
    extern __shared__ __align__(128) char smem[];
    uint32_t sb = smem_u32(smem);
    int tid = threadIdx.x;
    int wid = tid >> 5, lane = tid & 31;
    int m0 = blockIdx.x * 256, n0 = blockIdx.y * 128;
    int nk = K >> 5;

    load_stage(sb, Ahi, Alo, Bhi, Blo, K, m0, n0, 0, tid);
    CP_COMMIT();
    load_stage(sb + STAGE_B, Ahi, Alo, Bhi, Blo, K, m0, n0, 32, tid);
    CP_COMMIT();

    float acc[4][8][4];
#pragma unroll
    for (int i = 0; i < 4; i++)
#pragma unroll
        for (int j = 0; j < 8; j++)
#pragma unroll
            for (int q = 0; q < 4; q++) acc[i][j][q] = 0.f;

    int mo = (wid >> 1) * 64, no = (wid & 1) * 64;
    int a_row = mo + (lane & 15);
    int a_k8  = lane >> 4;
    int b_row = ((lane >> 4) << 3) + (lane & 7);
    int b_k8  = (lane >> 3) & 1;

    for (int k = 0; k < nk; k++) {
        if (k == nk - 1) { CP_WAIT0(); } else { CP_WAIT1(); }
        __syncthreads();
        int kn = k + 2;
        uint32_t base = sb + (uint32_t)(k % 3) * STAGE_B;
        if (kn < nk)
            load_stage(sb + (uint32_t)(kn % 3) * STAGE_B, Ahi, Alo, Bhi, Blo,
                       K, m0, n0, kn * 32, tid);
        CP_COMMIT();
#pragma unroll
        for (int k16 = 0; k16 < 2; k16++) {
            int kk8 = k16 * 2;
            uint32_t ah[4][4], al[4][4], bh[4][4], bl[4][4];
#pragma unroll
            for (int i = 0; i < 4; i++) {
                uint32_t aaddr = base + SO_AHI + (uint32_t)(a_row + i * 16) * RB
                               + (uint32_t)(kk8 + a_k8) * 16;
                ldm4(ah[i], aaddr);
                ldm4(al[i], aaddr + (SO_ALO - SO_AHI));
            }
#pragma unroll
            for (int j = 0; j < 4; j++) {
                uint32_t baddr = base + SO_BHI + (uint32_t)(no + j * 16 + b_row) * RB
                               + (uint32_t)(kk8 + b_k8) * 16;
                ldm4(bh[j], baddr);
                ldm4(bl[j], baddr + (SO_BLO - SO_BHI));
            }
#pragma unroll
            for (int i = 0; i < 4; i++)
#pragma unroll
                for (int j = 0; j < 4; j++) {
                    mma_bf16(acc[i][2 * j],     ah[i], &bh[j][0]);
                    mma_bf16(acc[i][2 * j + 1], ah[i], &bh[j][2]);
                    mma_bf16(acc[i][2 * j],     ah[i], &bl[j][0]);
                    mma_bf16(acc[i][2 * j + 1], ah[i], &bl[j][2]);
                    mma_bf16(acc[i][2 * j],     al[i], &bh[j][0]);
                    mma_bf16(acc[i][2 * j + 1], al[i], &bh[j][2]);
                }
        }
    }

    // epilogue
#pragma unroll
    for (int i = 0; i < 4; i++) {
        int r0 = m0 + mo + i * 16 + (lane >> 2);
#pragma unroll
        for (int half = 0; half < 2; half++) {
            int r = r0 + half * 8;
            if (r >= M) continue;
#pragma unroll
            for (int nb = 0; nb < 8; nb++) {
                int col = n0 + no + nb * 8 + 2 * (lane & 3);
                float v0 = acc[i][nb][half * 2 + 0];
                float v1 = acc[i][nb][half * 2 + 1];
                if (flags & 1) { v0 += bias[col]; v1 += bias[col + 1]; }
                if (flags & 4) {
                    float2 t = *(const float2*)(res + (size_t)r * N + col);
                    v0 += t.x; v1 += t.y;
                }
                if (flags & 2) { v0 = fmaxf(v0, 0.f); v1 = fmaxf(v1, 0.f); }
                if (flags & 8) {
                    __nv_bfloat16 h0, l0, h1, l1;
                    split2(v0, h0, l0);
                    split2(v1, h1, l1);
                    *(__nv_bfloat162*)(Chi + (size_t)r * N + col) = __halves2bfloat162(h0, h1);
                    *(__nv_bfloat162*)(Clo + (size_t)r * N + col) = __halves2bfloat162(l0, l1);
                } else {
                    *(float2*)(Cf + (size_t)r * N + col) = make_float2(v0, v1);
                }
            }
        }
    }
}

// ---------------- weight transpose+split: W[K,N] -> T[N,K] hi/lo --------------
__global__ void tsplit_kernel(const float* __restrict__ W,
                              __nv_bfloat16* __restrict__ thi, __nv_bfloat16* __restrict__ tlo,
                              int K, int N)
{
    int idx = blockIdx.x * 256 + threadIdx.x;
    if (idx >= K * N) return;
    int k = idx / N, n = idx % N;
    __nv_bfloat16 hi, lo;
    split2(W[idx], hi, lo);
    thi[(size_t)n * K + k] = hi;
    tlo[(size_t)n * K + k] = lo;
}

// ---------------- node encoder -------------------------------------------------
__global__ void enc_kernel(const float* __restrict__ xg, const float* __restrict__ W,
                           const float* __restrict__ b,
                           __nv_bfloat16* __restrict__ hi, __nv_bfloat16* __restrict__ lo)
{
    __shared__ float sx[16];
    int n = blockIdx.x, c = threadIdx.x;
    if (c < 16) sx[c] = xg[(size_t)n * 16 + c];
    __syncthreads();
    float v = b[c];
#pragma unroll
    for (int k = 0; k < 16; k++) v = fmaf(sx[k], W[k * H + c], v);
    __nv_bfloat16 h, l;
    split2(v, h, l);
    hi[(size_t)n * H + c] = h;
    lo[(size_t)n * H + c] = l;
}

// ---------------- tiny [E,4]@[4,4]+b projection -------------------------------
__global__ void basis4_kernel(const float* __restrict__ in, const float* __restrict__ W,
                              const float* __restrict__ b, float* __restrict__ out, int E)
{
    int e = blockIdx.x * blockDim.x + threadIdx.x;
    if (e >= E) return;
    float4 x = *(const float4*)(in + (size_t)e * 4);
    float o0 = b[0] + x.x * W[0] + x.y * W[4] + x.z * W[8]  + x.w * W[12];
    float o1 = b[1] + x.x * W[1] + x.y * W[5] + x.z * W[9]  + x.w * W[13];
    float o2 = b[2] + x.x * W[2] + x.y * W[6] + x.z * W[10] + x.w * W[14];
    float o3 = b[3] + x.x * W[3] + x.y * W[7] + x.z * W[11] + x.w * W[15];
    *(float4*)(out + (size_t)e * 4) = make_float4(o0, o1, o2, o3);
}

// ---------------- fused first-message (AB combined buffer, stride 512) --------
#define MEPB 16
__global__ __launch_bounds__(256) void msg_edge_kernel(
    const float* __restrict__ AB,
    const float* __restrict__ ea, const float* __restrict__ xlg,
    const float* __restrict__ Wc, const float* __restrict__ Wd,
    const float* __restrict__ bmsg,
    const int* __restrict__ srcg, const int* __restrict__ dstg,
    float* __restrict__ h, int Eg)
{
    __shared__ float sWc[16 * H];
    __shared__ float sWd[4 * H];
    __shared__ float sb[H];
    __shared__ float sea[MEPB][16];
    __shared__ float sxl[MEPB][4];
    int tid = threadIdx.x;
    for (int i = tid; i < 16 * H; i += 256) sWc[i] = Wc[i];
    for (int i = tid; i < 4 * H; i += 256) sWd[i] = Wd[i];
    sb[tid] = bmsg[tid];
    int e0 = blockIdx.x * MEPB;
    for (int i = tid; i < MEPB * 16; i += 256) {
        int e = e0 + i / 16;
        if (e < Eg) sea[i / 16][i % 16] = ea[(size_t)e * 16 + (i % 16)];
    }
    for (int i = tid; i < MEPB * 4; i += 256) {
        int e = e0 + i / 4;
        if (e < Eg) sxl[i / 4][i % 4] = xlg[(size_t)e * 4 + (i % 4)];
    }
    __syncthreads();
    int c = tid;
    for (int i = 0; i < MEPB; i++) {
        int e = e0 + i;
        if (e >= Eg) break;
        int s = srcg[e], d = dstg[e];
        float v = AB[(size_t)s * 512 + c] + AB[(size_t)d * 512 + 256 + c] + sb[c];
#pragma unroll
        for (int k = 0; k < 16; k++) v = fmaf(sea[i][k], sWc[k * H + c], v);
#pragma unroll
        for (int k = 0; k < 4; k++) v = fmaf(sxl[i][k], sWd[k * H + c], v);
        h[(size_t)e * H + c] = v;
    }
}

// ---------------- BN coefficient computation ----------------------------------
__global__ void bn_coef_kernel(const double* __restrict__ acc,
                               const float* __restrict__ gamma, const float* __restrict__ beta,
                               float* __restrict__ scale, float* __restrict__ shift, int M)
{
    int c = threadIdx.x;
    double mu = acc[c] / (double)M;
    double var = acc[H + c] / (double)M - mu * mu;
    float inv = rsqrtf((float)var + 1e-5f);
    float sc = gamma[c] * inv;
    scale[c] = sc;
    shift[c] = beta[c] - (float)mu * sc;
}

// ---------------- fused GENConv aggregation -----------------------------------
#define AEPB 8
__global__ __launch_bounds__(256) void genAB_kernel(
    const float* __restrict__ x, const float* __restrict__ nbg, const float* __restrict__ ebg,
    const float* __restrict__ Wnb, const float* __restrict__ bnb,
    const float* __restrict__ Web, const float* __restrict__ beb,
    const float* __restrict__ bnscale, const float* __restrict__ bnshift,
    const int* __restrict__ src, const int* __restrict__ dst,
    float* __restrict__ svec, float* __restrict__ wvec, int Elg, int use_bn)
{
    __shared__ float sWn[4 * H], sWe[4 * H], sbn[H], sbe[H];
    int tid = threadIdx.x;
    for (int i = tid; i < 4 * H; i += 256) { sWn[i] = Wnb[i]; sWe[i] = Web[i]; }
    sbn[tid] = bnb[tid];
    sbe[tid] = beb[tid];
    __syncthreads();
    int c = tid;
    float sc = 1.f, sh = 0.f;
    if (use_bn) { sc = bnscale[c]; sh = bnshift[c]; }
    int e0 = blockIdx.x * AEPB;
    for (int i = 0; i < AEPB; i++) {
        int e = e0 + i;
        if (e >= Elg) break;
        int s = src[e], d = dst[e];
        float4 nv = *(const float4*)(nbg + (size_t)s * 4);
        float4 ev4 = *(const float4*)(ebg + (size_t)e * 4);
        float nbv = sbn[c];
        nbv = fmaf(nv.x, sWn[c], nbv);
        nbv = fmaf(nv.y, sWn[H + c], nbv);
        nbv = fmaf(nv.z, sWn[2 * H + c], nbv);
        nbv = fmaf(nv.w, sWn[3 * H + c], nbv);
        float ebv = sbe[c];
        ebv = fmaf(ev4.x, sWe[c], ebv);
        ebv = fmaf(ev4.y, sWe[H + c], ebv);
        ebv = fmaf(ev4.z, sWe[2 * H + c], ebv);
        ebv = fmaf(ev4.w, sWe[3 * H + c], ebv);
        float xv = x[(size_t)s * H + c];
        if (use_bn) xv = fmaxf(fmaf(xv, sc, sh), 0.f);
        float mv = fmaxf(xv + nbv + ebv, 0.f) + 1e-7f;
        float ev = expf(fminf(mv, 80.f));
        atomicAdd(svec + (size_t)d * H + c, ev);
        atomicAdd(wvec + (size_t)d * H + c, ev * mv);
    }
}

// ---------------- GENConv combine: hpre = BN?(x) + w/(s+eps) -> split bf16 ----
__global__ void genD_kernel(const float* __restrict__ x, const float* __restrict__ svec,
                            const float* __restrict__ wvec,
                            const float* __restrict__ bnscale, const float* __restrict__ bnshift,
                            __nv_bfloat16* __restrict__ ahi, __nv_bfloat16* __restrict__ alo,
                            int use_bn)
{
    int c = threadIdx.x;
    size_t i = (size_t)blockIdx.x * H + c;
    float xv = x[i];
    if (use_bn) xv = fmaxf(fmaf(xv, bnscale[c], bnshift[c]), 0.f);
    float v = xv + wvec[i] / (svec[i] + 1e-16f);
    __nv_bfloat16 h, l;
    split2(v, h, l);
    ahi[i] = h;
    alo[i] = l;
}

// ---------------- BatchNorm statistics ----------------------------------------
__global__ void bn_stats_kernel(const float* __restrict__ h, int M, double* __restrict__ acc)
{
    int c = threadIdx.x;
    float s = 0.f, s2 = 0.f;
    for (int r = blockIdx.x; r < M; r += gridDim.x) {
        float v = h[(size_t)r * H + c];
        s += v;
        s2 = fmaf(v, v, s2);
    }
    atomicAdd(&acc[c], (double)s);
    atomicAdd(&acc[H + c], (double)s2);
}

// ---------------- final scatter (BN fused) / pooling / prediction -------------
__global__ __launch_bounds__(256) void scatter_bn_kernel(
    const float* __restrict__ h, const float* __restrict__ bnscale,
    const float* __restrict__ bnshift, const int* __restrict__ dstg,
    float* __restrict__ node_emb, int Eg)
{
    int c = threadIdx.x;
    float sc = bnscale[c], sh = bnshift[c];
    int e0 = blockIdx.x * AEPB;
    for (int i = 0; i < AEPB; i++) {
        int e = e0 + i;
        if (e >= Eg) break;
        float v = fmaf(h[(size_t)e * H + c], sc, sh);
        atomicAdd(node_emb + (size_t)dstg[e] * H + c, v);
    }
}

__global__ void pool_kernel(const float* __restrict__ node_emb, const int* __restrict__ batch,
                            float* __restrict__ gsum, float* __restrict__ cnt)
{
    int n = blockIdx.x;
    int c = threadIdx.x;
    int b = batch[n];
    atomicAdd(gsum + (size_t)b * H + c, node_emb[(size_t)n * H + c]);
    if (c == 0) atomicAdd(&cnt[b], 1.0f);
}

__global__ void predict_kernel(const float* __restrict__ gsum, const float* __restrict__ cnt,
                               const float* __restrict__ Wp, const float* __restrict__ bp,
                               float* __restrict__ out)
{
    int g = blockIdx.x, c = threadIdx.x;
    float v = gsum[(size_t)g * H + c] * Wp[c];
    __shared__ float red[8];
#pragma unroll
    for (int o = 16; o > 0; o >>= 1) v += __shfl_down_sync(0xffffffffu, v, o);
    if ((c & 31) == 0) red[c >> 5] = v;
    __syncthreads();
    if (c == 0) {
        float t = 0.f;
#pragma unroll
        for (int i = 0; i < 8; i++) t += red[i];
        out[g] = t / fmaxf(cnt[g], 1.0f) + bp[0];
    }
}

// -------------------------------------------------------------------------------
static void* symA(const void* sym)
{
    void* p = nullptr;
    cudaGetSymbolAddress(&p, sym);
    return p;
}

extern "C" void kernel_launch(void* const* d_in, const int* in_sizes, int n_in,
                              void* d_out, int out_size)
{
    const float* x_g       = (const float*)d_in[0];
    const float* ea_g      = (const float*)d_in[1];
    const float* x_lg      = (const float*)d_in[2];
    const float* edb       = (const float*)d_in[3];
    const float* ea_lg     = (const float*)d_in[4];
    const float* W_enc     = (const float*)d_in[5];
    const float* b_enc     = (const float*)d_in[6];
    const float* W_msg     = (const float*)d_in[7];
    const float* b_msg     = (const float*)d_in[8];
    const float* Wg_nb     = (const float*)d_in[9];
    const float* bg_nb     = (const float*)d_in[10];
    const float* Wg_eb     = (const float*)d_in[11];
    const float* bg_eb     = (const float*)d_in[12];
    const float* Wl_nb     = (const float*)d_in[13];
    const float* bl_nb     = (const float*)d_in[14];
    const float* Wl_eb     = (const float*)d_in[15];
    const float* bl_eb     = (const float*)d_in[16];
    const float* W1        = (const float*)d_in[17];
    const float* b1        = (const float*)d_in[18];
    const float* W2        = (const float*)d_in[19];
    const float* b2        = (const float*)d_in[20];
    const float* bn_gamma  = (const float*)d_in[21];
    const float* bn_beta   = (const float*)d_in[22];
    const float* W_pred    = (const float*)d_in[23];
    const float* b_pred    = (const float*)d_in[24];
    const int*   eig       = (const int*)d_in[25];
    const int*   eil       = (const int*)d_in[26];
    const int*   batch     = (const int*)d_in[27];

    int N   = in_sizes[0] / 16;   // 20000
    int Eg  = in_sizes[1] / 16;   // 200000
    int Elg = in_sizes[4] / 4;    // 400000
    const int L = 4;

    cudaFuncSetAttribute(mma_gemm_kernel, cudaFuncAttributeMaxDynamicSharedMemorySize,
                         GEMM_SMEM);

    float* p_AB   = (float*)symA(g_AB);
    float* p_h    = (float*)symA(g_h);
    float* p_s    = (float*)symA(g_s);
    float* p_w    = (float*)symA(g_w);
    float* p_nbg  = (float*)symA(g_nbg);
    float* p_ebg  = (float*)symA(g_ebg);
    float* p_ne   = (float*)symA(g_nodeemb);
    double* p_bnacc = (double*)symA(g_bnacc);
    float* p_bnsc = (float*)symA(g_bnscale);
    float* p_bnsh = (float*)symA(g_bnshift);
    float* p_gsum = (float*)symA(g_gsum);
    float* p_cnt  = (float*)symA(g_cnt);

    __nv_bfloat16* p_node_hi = (__nv_bfloat16*)symA(g_node_hi);
    __nv_bfloat16* p_node_lo = (__nv_bfloat16*)symA(g_node_lo);
    __nv_bfloat16* p_act_hi  = (__nv_bfloat16*)symA(g_act_hi);
    __nv_bfloat16* p_act_lo  = (__nv_bfloat16*)symA(g_act_lo);
    __nv_bfloat16* p_hid_hi  = (__nv_bfloat16*)symA(g_hid_hi);
    __nv_bfloat16* p_hid_lo  = (__nv_bfloat16*)symA(g_hid_lo);
    __nv_bfloat16* p_wthi    = (__nv_bfloat16*)symA(g_wthi);
    __nv_bfloat16* p_wtlo    = (__nv_bfloat16*)symA(g_wtlo);

    const int* src_g = eig;
    const int* dst_g = eig + Eg;
    const int* src_l = eil;
    const int* dst_l = eil + Elg;

    int mtE = (Eg + 255) / 256;   // 782
    int mtN = (N + 255) / 256;    // 79

    // --- weight transpose + split ---
    tsplit_kernel<<<(65536 + 255) / 256, 256>>>(W_msg,           p_wthi + OFF_WMSG,         p_wtlo + OFF_WMSG,         256, 256);
    tsplit_kernel<<<(65536 + 255) / 256, 256>>>(W_msg + 256 * H, p_wthi + OFF_WMSG + 65536, p_wtlo + OFF_WMSG + 65536, 256, 256);
    for (int l = 0; l < L; l++) {
        tsplit_kernel<<<(131072 + 255) / 256, 256>>>(
            W1 + (size_t)l * 131072, p_wthi + OFF_W1T + l * 131072, p_wtlo + OFF_W1T + l * 131072, 256, 512);
        tsplit_kernel<<<(131072 + 255) / 256, 256>>>(
            W2 + (size_t)l * 131072, p_wthi + OFF_W2T + l * 131072, p_wtlo + OFF_W2T + l * 131072, 512, 256);
    }

    // --- node encoder + combined msg GEMM (N=512) ---
    enc_kernel<<<N, 256>>>(x_g, W_enc, b_enc, p_node_hi, p_node_lo);
    {
        dim3 grid(mtN, 4);
        mma_gemm_kernel<<<grid, 256, GEMM_SMEM>>>(
            p_node_hi, p_node_lo, p_wthi + OFF_WMSG, p_wtlo + OFF_WMSG,
            nullptr, nullptr, p_AB, nullptr, nullptr, N, 512, 256, 0);
    }
    basis4_kernel<<<(Eg + 255) / 256, 256>>>(edb,   Wg_nb, bg_nb, p_nbg, Eg);
    basis4_kernel<<<(Elg + 255) / 256, 256>>>(ea_lg, Wg_eb, bg_eb, p_ebg, Elg);
    msg_edge_kernel<<<(Eg + MEPB - 1) / MEPB, 256>>>(
        p_AB, ea_g, x_lg, W_msg + 512 * H, W_msg + 528 * H, b_msg,
        src_g, dst_g, p_h, Eg);

    // --- 4 GENConv layers ---
    for (int l = 0; l < L; l++) {
        int use_bn = (l > 0) ? 1 : 0;
        if (use_bn) {
            cudaMemsetAsync(p_bnacc, 0, 2 * H * sizeof(double));
            bn_stats_kernel<<<1024, 256>>>(p_h, Eg, p_bnacc);
            bn_coef_kernel<<<1, 256>>>(p_bnacc, bn_gamma + (l - 1) * H, bn_beta + (l - 1) * H,
                                       p_bnsc, p_bnsh, Eg);
        }
        cudaMemsetAsync(p_s, 0, (size_t)Eg * H * sizeof(float));
        cudaMemsetAsync(p_w, 0, (size_t)Eg * H * sizeof(float));
        genAB_kernel<<<(Elg + AEPB - 1) / AEPB, 256>>>(
            p_h, p_nbg, p_ebg,
            Wl_nb + l * 4 * H, bl_nb + l * H,
            Wl_eb + l * 4 * H, bl_eb + l * H,
            p_bnsc, p_bnsh, src_l, dst_l, p_s, p_w, Elg, use_bn);
        genD_kernel<<<Eg, 256>>>(p_h, p_s, p_w, p_bnsc, p_bnsh, p_act_hi, p_act_lo, use_bn);

        // GEMM1: hidden = relu(hpre @ W1 + b1), split bf16 out
        {
            dim3 grid(mtE, 4);
            mma_gemm_kernel<<<grid, 256, GEMM_SMEM>>>(
                p_act_hi, p_act_lo, p_wthi + OFF_W1T + l * 131072, p_wtlo + OFF_W1T + l * 131072,
                b1 + l * 512, nullptr, nullptr, p_hid_hi, p_hid_lo,
                Eg, 512, 256, 1 | 2 | 8);
        }
        // GEMM2: h = hidden @ W2 + b2 (+ residual for l>0), fp32 out
        {
            dim3 grid(mtE, 2);
            mma_gemm_kernel<<<grid, 256, GEMM_SMEM>>>(
                p_hid_hi, p_hid_lo, p_wthi + OFF_W2T + l * 131072, p_wtlo + OFF_W2T + l * 131072,
                b2 + l * 256, (l > 0) ? p_h : nullptr, p_h, nullptr, nullptr,
                Eg, 256, 512, (l > 0) ? (1 | 4) : 1);
        }
    }

    // --- final BN coefs + fused scatter ---
    cudaMemsetAsync(p_bnacc, 0, 2 * H * sizeof(double));
    bn_stats_kernel<<<1024, 256>>>(p_h, Eg, p_bnacc);
    bn_coef_kernel<<<1, 256>>>(p_bnacc, bn_gamma + 3 * H, bn_beta + 3 * H, p_bnsc, p_bnsh, Eg);

    cudaMemsetAsync(p_ne,   0, (size_t)N * H * sizeof(float));
    cudaMemsetAsync(p_gsum, 0, NGRAPH * H * sizeof(float));
    cudaMemsetAsync(p_cnt,  0, NGRAPH * sizeof(float));
    scatter_bn_kernel<<<(Eg + AEPB - 1) / AEPB, 256>>>(p_h, p_bnsc, p_bnsh, dst_g, p_ne, Eg);
    pool_kernel<<<N, 256>>>(p_ne, batch, p_gsum, p_cnt);
    predict_kernel<<<NGRAPH, 256>>>(p_gsum, p_cnt, W_pred, b_pred, (float*)d_out);
}

// round 6
// speedup vs baseline: 2.1386x; 1.1663x over previous
#include <cuda_runtime.h>
#include <cuda_bf16.h>
#include <cstdint>

#define H 256
#define NGRAPH 128
#define MAXN   20224
#define MAXEG  200192
#define MAXELG 400128

// ---------------- scratch ----------------
__device__ float g_AB[(size_t)MAXN * 512];
__device__ float g_h[(size_t)MAXEG * H];
__device__ float g_nbg[(size_t)MAXEG * 4];
__device__ float g_ebg[(size_t)MAXELG * 4];
__device__ float g_nodeemb[(size_t)MAXN * H];
__device__ double g_bnacc[2 * H];
__device__ float g_bnscale[H];
__device__ float g_bnshift[H];
__device__ float g_gsum[NGRAPH * H];
__device__ float g_cnt[NGRAPH];

// CSR scratch
__device__ int g_deg[MAXEG];
__device__ int g_cursor[MAXEG];
__device__ int g_blk[1024];
__device__ int g_rowptr_lg[MAXEG + 1];
__device__ int g_eidx_lg[MAXELG];
__device__ int g_rowptr_g[MAXN + 1];
__device__ int g_eidx_g[MAXEG];

// bf16 split buffers (pad rows beyond M are never written -> stay zero)
__device__ __nv_bfloat16 g_node_hi[(size_t)MAXN * H];
__device__ __nv_bfloat16 g_node_lo[(size_t)MAXN * H];
__device__ __nv_bfloat16 g_act_hi[(size_t)MAXEG * H];
__device__ __nv_bfloat16 g_act_lo[(size_t)MAXEG * H];
__device__ __nv_bfloat16 g_hid_hi[(size_t)MAXEG * 2 * H];
__device__ __nv_bfloat16 g_hid_lo[(size_t)MAXEG * 2 * H];

// transposed/split weights arena
#define OFF_WMSG 0
#define OFF_W1T  (512 * 256)
#define OFF_W2T  (OFF_W1T + 4 * 131072)
#define WT_TOTAL (OFF_W2T + 4 * 131072)
__device__ __nv_bfloat16 g_wthi[WT_TOTAL];
__device__ __nv_bfloat16 g_wtlo[WT_TOTAL];

// ======================= helpers =======================
__device__ __forceinline__ uint32_t smem_u32(const void* p) {
    uint32_t a;
    asm("{ .reg .u64 t; cvta.to.shared.u64 t, %1; cvt.u32.u64 %0, t; }" : "=r"(a) : "l"(p));
    return a;
}
#define CP16(dst, src) \
    asm volatile("cp.async.cg.shared.global [%0], [%1], 16;" :: "r"(dst), "l"(src) : "memory")
#define CP_COMMIT() asm volatile("cp.async.commit_group;" ::: "memory")
#define CP_WAIT0()  asm volatile("cp.async.wait_group 0;" ::: "memory")

__device__ __forceinline__ void ldm4(uint32_t (&r)[4], uint32_t addr) {
    asm volatile("ldmatrix.sync.aligned.m8n8.x4.shared.b16 {%0,%1,%2,%3}, [%4];"
                 : "=r"(r[0]), "=r"(r[1]), "=r"(r[2]), "=r"(r[3]) : "r"(addr));
}
__device__ __forceinline__ void mma_bf16(float (&d)[4], const uint32_t (&a)[4], const uint32_t* b) {
    asm volatile(
        "mma.sync.aligned.m16n8k16.row.col.f32.bf16.bf16.f32 "
        "{%0,%1,%2,%3}, {%4,%5,%6,%7}, {%8,%9}, {%0,%1,%2,%3};"
        : "+f"(d[0]), "+f"(d[1]), "+f"(d[2]), "+f"(d[3])
        : "r"(a[0]), "r"(a[1]), "r"(a[2]), "r"(a[3]), "r"(b[0]), "r"(b[1]));
}
__device__ __forceinline__ void split2(float v, __nv_bfloat16& hi, __nv_bfloat16& lo) {
    hi = __float2bfloat16(v);
    lo = __float2bfloat16(v - __bfloat162float(hi));
}

// ======================= CSR build kernels =======================
__global__ void zero_int_kernel(int* a, int n)
{
    int i = blockIdx.x * 256 + threadIdx.x;
    if (i < n) a[i] = 0;
}
__global__ void hist_kernel(const int* __restrict__ dst, int* __restrict__ deg, int E)
{
    int i = blockIdx.x * 256 + threadIdx.x;
    if (i < E) atomicAdd(&deg[dst[i]], 1);
}
__global__ void scan_block_sums(const int* __restrict__ deg, int* __restrict__ blk, int n)
{
    __shared__ int sd[256];
    int t = threadIdx.x;
    int i = blockIdx.x * 256 + t;
    sd[t] = (i < n) ? deg[i] : 0;
    __syncthreads();
    for (int o = 128; o > 0; o >>= 1) {
        if (t < o) sd[t] += sd[t + o];
        __syncthreads();
    }
    if (t == 0) blk[blockIdx.x] = sd[0];
}
__global__ void scan_single_block(int* blk, int nb)
{
    __shared__ int tmp[1024];
    int t = threadIdx.x;
    int v = (t < nb) ? blk[t] : 0;
    tmp[t] = v;
    __syncthreads();
    for (int o = 1; o < 1024; o <<= 1) {
        int u = (t >= o) ? tmp[t - o] : 0;
        __syncthreads();
        tmp[t] += u;
        __syncthreads();
    }
    if (t < nb) blk[t] = tmp[t] - v;
}
__global__ void scan_final(const int* __restrict__ deg, const int* __restrict__ blk,
                           int* __restrict__ rowptr, int* __restrict__ cursor, int n, int E)
{
    __shared__ int tmp[256];
    int t = threadIdx.x;
    int i = blockIdx.x * 256 + t;
    int v = (i < n) ? deg[i] : 0;
    tmp[t] = v;
    __syncthreads();
    for (int o = 1; o < 256; o <<= 1) {
        int u = (t >= o) ? tmp[t - o] : 0;
        __syncthreads();
        tmp[t] += u;
        __syncthreads();
    }
    int excl = tmp[t] - v + blk[blockIdx.x];
    if (i < n) { rowptr[i] = excl; cursor[i] = excl; }
    if (blockIdx.x == 0 && t == 0) rowptr[n] = E;
}
__global__ void fill_csr_kernel(const int* __restrict__ dst, int* __restrict__ cursor,
                                int* __restrict__ eidx, int E)
{
    int e = blockIdx.x * 256 + threadIdx.x;
    if (e < E) {
        int p = atomicAdd(&cursor[dst[e]], 1);
        eidx[p] = e;
    }
}

// ======================= mma.sync split-bf16 GEMM =======================
// CTA 128x128, 8 warps of 64x32, BK=32, 2 stages, 2 CTAs/SM.
// flags: 1=bias, 2=relu, 4=residual(fp32 [M,N]), 8=split-out bf16 (else fp32 out)
#define RB 80
#define TILE_B (128 * RB)
#define SO_AHI 0
#define SO_ALO (1 * TILE_B)
#define SO_BHI (2 * TILE_B)
#define SO_BLO (3 * TILE_B)
#define STAGE_B (4 * TILE_B)        // 40960
#define GEMM_SMEM (2 * STAGE_B)     // 81920

__device__ __forceinline__ void load_stage(uint32_t sbase,
    const __nv_bfloat16* __restrict__ A_hi, const __nv_bfloat16* __restrict__ A_lo,
    const __nv_bfloat16* __restrict__ B_hi, const __nv_bfloat16* __restrict__ B_lo,
    int K, int m0, int n0, int k0, int tid)
{
#pragma unroll
    for (int i = 0; i < 2; i++) {
        int g = tid + i * 256;
        int row = g >> 2, ch = g & 3;
        uint32_t so = (uint32_t)row * RB + (uint32_t)ch * 16;
        size_t ao = (size_t)(m0 + row) * K + k0 + ch * 8;
        size_t bo = (size_t)(n0 + row) * K + k0 + ch * 8;
        CP16(sbase + SO_AHI + so, A_hi + ao);
        CP16(sbase + SO_ALO + so, A_lo + ao);
        CP16(sbase + SO_BHI + so, B_hi + bo);
        CP16(sbase + SO_BLO + so, B_lo + bo);
    }
}

__global__ __launch_bounds__(256, 2) void mma_gemm_kernel(
    const __nv_bfloat16* __restrict__ Ahi, const __nv_bfloat16* __restrict__ Alo,
    const __nv_bfloat16* __restrict__ Bhi, const __nv_bfloat16* __restrict__ Blo,
    const float* __restrict__ bias, const float* __restrict__ res,
    float* __restrict__ Cf, __nv_bfloat16* __restrict__ Chi, __nv_bfloat16* __restrict__ Clo,
    int M, int N, int K, int flags)
{
    extern __shared__ __align__(128) char smem[];
    uint32_t sb = smem_u32(smem);
    int tid = threadIdx.x;
    int wid = tid >> 5, lane = tid & 31;
    int m0 = blockIdx.x * 128, n0 = blockIdx.y * 128;
    int nk = K >> 5;

    load_stage(sb, Ahi, Alo, Bhi, Blo, K, m0, n0, 0, tid);
    CP_COMMIT();

    float acc[4][4][4];
#pragma unroll
    for (int i = 0; i < 4; i++)
#pragma unroll
        for (int j = 0; j < 4; j++)
#pragma unroll
            for (int q = 0; q < 4; q++) acc[i][j][q] = 0.f;

    int mo = (wid & 1) * 64, no = (wid >> 1) * 32;
    int a_row = mo + (lane & 15);
    int a_k8  = lane >> 4;
    int b_row = ((lane >> 4) << 3) + (lane & 7);
    int b_k8  = (lane >> 3) & 1;

    for (int k = 0; k < nk; k++) {
        CP_WAIT0();
        __syncthreads();
        uint32_t base = sb + (uint32_t)(k & 1) * STAGE_B;
        if (k + 1 < nk)
            load_stage(sb + (uint32_t)((k + 1) & 1) * STAGE_B, Ahi, Alo, Bhi, Blo,
                       K, m0, n0, (k + 1) * 32, tid);
        CP_COMMIT();
#pragma unroll
        for (int k16 = 0; k16 < 2; k16++) {
            int kk8 = k16 * 2;
            uint32_t ah[4][4], al[4][4];
#pragma unroll
            for (int i = 0; i < 4; i++) {
                uint32_t aaddr = base + SO_AHI + (uint32_t)(a_row + i * 16) * RB
                               + (uint32_t)(kk8 + a_k8) * 16;
                ldm4(ah[i], aaddr);
                ldm4(al[i], aaddr + (SO_ALO - SO_AHI));
            }
#pragma unroll
            for (int j = 0; j < 2; j++) {
                uint32_t bh[4], bl[4];
                uint32_t baddr = base + SO_BHI + (uint32_t)(no + j * 16 + b_row) * RB
                               + (uint32_t)(kk8 + b_k8) * 16;
                ldm4(bh, baddr);
                ldm4(bl, baddr + (SO_BLO - SO_BHI));
#pragma unroll
                for (int i = 0; i < 4; i++) {
                    mma_bf16(acc[i][2 * j],     ah[i], &bh[0]);
                    mma_bf16(acc[i][2 * j + 1], ah[i], &bh[2]);
                    mma_bf16(acc[i][2 * j],     ah[i], &bl[0]);
                    mma_bf16(acc[i][2 * j + 1], ah[i], &bl[2]);
                    mma_bf16(acc[i][2 * j],     al[i], &bh[0]);
                    mma_bf16(acc[i][2 * j + 1], al[i], &bh[2]);
                }
            }
        }
    }

    // epilogue
#pragma unroll
    for (int i = 0; i < 4; i++) {
        int r0 = m0 + mo + i * 16 + (lane >> 2);
#pragma unroll
        for (int half = 0; half < 2; half++) {
            int r = r0 + half * 8;
            if (r >= M) continue;
#pragma unroll
            for (int nb = 0; nb < 4; nb++) {
                int col = n0 + no + nb * 8 + 2 * (lane & 3);
                float v0 = acc[i][nb][half * 2 + 0];
                float v1 = acc[i][nb][half * 2 + 1];
                if (flags & 1) { v0 += bias[col]; v1 += bias[col + 1]; }
                if (flags & 4) {
                    float2 t = *(const float2*)(res + (size_t)r * N + col);
                    v0 += t.x; v1 += t.y;
                }
                if (flags & 2) { v0 = fmaxf(v0, 0.f); v1 = fmaxf(v1, 0.f); }
                if (flags & 8) {
                    __nv_bfloat16 h0, l0, h1, l1;
                    split2(v0, h0, l0);
                    split2(v1, h1, l1);
                    *(__nv_bfloat162*)(Chi + (size_t)r * N + col) = __halves2bfloat162(h0, h1);
                    *(__nv_bfloat162*)(Clo + (size_t)r * N + col) = __halves2bfloat162(l0, l1);
                } else {
                    *(float2*)(Cf + (size_t)r * N + col) = make_float2(v0, v1);
                }
            }
        }
    }
}

// ---------------- weight transpose+split ---------------------------------------
__global__ void tsplit_kernel(const float* __restrict__ W,
                              __nv_bfloat16* __restrict__ thi, __nv_bfloat16* __restrict__ tlo,
                              int K, int N)
{
    int idx = blockIdx.x * 256 + threadIdx.x;
    if (idx >= K * N) return;
    int k = idx / N, n = idx % N;
    __nv_bfloat16 hi, lo;
    split2(W[idx], hi, lo);
    thi[(size_t)n * K + k] = hi;
    tlo[(size_t)n * K + k] = lo;
}

// ---------------- node encoder -------------------------------------------------
__global__ void enc_kernel(const float* __restrict__ xg, const float* __restrict__ W,
                           const float* __restrict__ b,
                           __nv_bfloat16* __restrict__ hi, __nv_bfloat16* __restrict__ lo)
{
    __shared__ float sx[16];
    int n = blockIdx.x, c = threadIdx.x;
    if (c < 16) sx[c] = xg[(size_t)n * 16 + c];
    __syncthreads();
    float v = b[c];
#pragma unroll
    for (int k = 0; k < 16; k++) v = fmaf(sx[k], W[k * H + c], v);
    __nv_bfloat16 h, l;
    split2(v, h, l);
    hi[(size_t)n * H + c] = h;
    lo[(size_t)n * H + c] = l;
}

// ---------------- tiny [E,4]@[4,4]+b projection --------------------------------
__global__ void basis4_kernel(const float* __restrict__ in, const float* __restrict__ W,
                              const float* __restrict__ b, float* __restrict__ out, int E)
{
    int e = blockIdx.x * blockDim.x + threadIdx.x;
    if (e >= E) return;
    float4 x = *(const float4*)(in + (size_t)e * 4);
    float o0 = b[0] + x.x * W[0] + x.y * W[4] + x.z * W[8]  + x.w * W[12];
    float o1 = b[1] + x.x * W[1] + x.y * W[5] + x.z * W[9]  + x.w * W[13];
    float o2 = b[2] + x.x * W[2] + x.y * W[6] + x.z * W[10] + x.w * W[14];
    float o3 = b[3] + x.x * W[3] + x.y * W[7] + x.z * W[11] + x.w * W[15];
    *(float4*)(out + (size_t)e * 4) = make_float4(o0, o1, o2, o3);
}

// ---------------- fused first-message ------------------------------------------
#define MEPB 16
__global__ __launch_bounds__(256) void msg_edge_kernel(
    const float* __restrict__ AB,
    const float* __restrict__ ea, const float* __restrict__ xlg,
    const float* __restrict__ Wc, const float* __restrict__ Wd,
    const float* __restrict__ bmsg,
    const int* __restrict__ srcg, const int* __restrict__ dstg,
    float* __restrict__ h, int Eg)
{
    __shared__ float sWc[16 * H];
    __shared__ float sWd[4 * H];
    __shared__ float sb[H];
    __shared__ float sea[MEPB][16];
    __shared__ float sxl[MEPB][4];
    int tid = threadIdx.x;
    for (int i = tid; i < 16 * H; i += 256) sWc[i] = Wc[i];
    for (int i = tid; i < 4 * H; i += 256) sWd[i] = Wd[i];
    sb[tid] = bmsg[tid];
    int e0 = blockIdx.x * MEPB;
    for (int i = tid; i < MEPB * 16; i += 256) {
        int e = e0 + i / 16;
        if (e < Eg) sea[i / 16][i % 16] = ea[(size_t)e * 16 + (i % 16)];
    }
    for (int i = tid; i < MEPB * 4; i += 256) {
        int e = e0 + i / 4;
        if (e < Eg) sxl[i / 4][i % 4] = xlg[(size_t)e * 4 + (i % 4)];
    }
    __syncthreads();
    int c = tid;
    for (int i = 0; i < MEPB; i++) {
        int e = e0 + i;
        if (e >= Eg) break;
        int s = srcg[e], d = dstg[e];
        float v = AB[(size_t)s * 512 + c] + AB[(size_t)d * 512 + 256 + c] + sb[c];
#pragma unroll
        for (int k = 0; k < 16; k++) v = fmaf(sea[i][k], sWc[k * H + c], v);
#pragma unroll
        for (int k = 0; k < 4; k++) v = fmaf(sxl[i][k], sWd[k * H + c], v);
        h[(size_t)e * H + c] = v;
    }
}

// ---------------- BN coefficient computation -----------------------------------
__global__ void bn_coef_kernel(const double* __restrict__ acc,
                               const float* __restrict__ gamma, const float* __restrict__ beta,
                               float* __restrict__ scale, float* __restrict__ shift, int M)
{
    int c = threadIdx.x;
    double mu = acc[c] / (double)M;
    double var = acc[H + c] / (double)M - mu * mu;
    float inv = rsqrtf((float)var + 1e-5f);
    float sc = gamma[c] * inv;
    scale[c] = sc;
    shift[c] = beta[c] - (float)mu * sc;
}

// ---------------- fused GENConv aggregation (CSR gather, no atomics) -----------
// per dst row d: loop in-edges; m=relu(BN?(x[src])+nb(src)+eb(e))+eps;
// se+=exp(m); sw+=exp(m)*m; out = BN?(x[d]) + sw/(se+eps) -> split bf16
__global__ __launch_bounds__(256) void gen_aggr_kernel(
    const float* __restrict__ x, const float* __restrict__ nbg, const float* __restrict__ ebg,
    const float* __restrict__ Wnb, const float* __restrict__ bnb,
    const float* __restrict__ Web, const float* __restrict__ beb,
    const float* __restrict__ bnscale, const float* __restrict__ bnshift,
    const int* __restrict__ src, const int* __restrict__ rowptr, const int* __restrict__ eidx,
    __nv_bfloat16* __restrict__ ahi, __nv_bfloat16* __restrict__ alo, int use_bn)
{
    __shared__ float sWn[4 * H], sWe[4 * H], sbn[H], sbe[H];
    int tid = threadIdx.x;
    for (int i = tid; i < 4 * H; i += 256) { sWn[i] = Wnb[i]; sWe[i] = Web[i]; }
    sbn[tid] = bnb[tid];
    sbe[tid] = beb[tid];
    __syncthreads();
    int d = blockIdx.x, c = tid;
    float sc = 1.f, sh = 0.f;
    if (use_bn) { sc = bnscale[c]; sh = bnshift[c]; }
    int beg = rowptr[d], end = rowptr[d + 1];
    float se = 0.f, sw = 0.f;
    for (int p = beg; p < end; p++) {
        int e = eidx[p];
        int s = src[e];
        float4 nv = *(const float4*)(nbg + (size_t)s * 4);
        float4 ev4 = *(const float4*)(ebg + (size_t)e * 4);
        float nbv = sbn[c];
        nbv = fmaf(nv.x, sWn[c], nbv);
        nbv = fmaf(nv.y, sWn[H + c], nbv);
        nbv = fmaf(nv.z, sWn[2 * H + c], nbv);
        nbv = fmaf(nv.w, sWn[3 * H + c], nbv);
        float ebv = sbe[c];
        ebv = fmaf(ev4.x, sWe[c], ebv);
        ebv = fmaf(ev4.y, sWe[H + c], ebv);
        ebv = fmaf(ev4.z, sWe[2 * H + c], ebv);
        ebv = fmaf(ev4.w, sWe[3 * H + c], ebv);
        float xv = x[(size_t)s * H + c];
        if (use_bn) xv = fmaxf(fmaf(xv, sc, sh), 0.f);
        float mv = fmaxf(xv + nbv + ebv, 0.f) + 1e-7f;
        float ee = expf(fminf(mv, 80.f));
        se += ee;
        sw += ee * mv;
    }
    float xv = x[(size_t)d * H + c];
    if (use_bn) xv = fmaxf(fmaf(xv, sc, sh), 0.f);
    float v = xv + sw / (se + 1e-16f);
    __nv_bfloat16 hh, ll;
    split2(v, hh, ll);
    size_t i = (size_t)d * H + c;
    ahi[i] = hh;
    alo[i] = ll;
}

// ---------------- BatchNorm statistics -----------------------------------------
__global__ void bn_stats_kernel(const float* __restrict__ h, int M, double* __restrict__ acc)
{
    int c = threadIdx.x;
    float s = 0.f, s2 = 0.f;
    for (int r = blockIdx.x; r < M; r += gridDim.x) {
        float v = h[(size_t)r * H + c];
        s += v;
        s2 = fmaf(v, v, s2);
    }
    atomicAdd(&acc[c], (double)s);
    atomicAdd(&acc[H + c], (double)s2);
}

// ---------------- node gather (BN fused, CSR over dst_g) -----------------------
__global__ void node_gather_kernel(const float* __restrict__ h,
                                   const float* __restrict__ bnscale,
                                   const float* __restrict__ bnshift,
                                   const int* __restrict__ rowptr, const int* __restrict__ eidx,
                                   float* __restrict__ node_emb)
{
    int n = blockIdx.x, c = threadIdx.x;
    float sc = bnscale[c], sh = bnshift[c];
    int beg = rowptr[n], end = rowptr[n + 1];
    float acc = 0.f;
    for (int p = beg; p < end; p++) {
        int e = eidx[p];
        acc += fmaf(h[(size_t)e * H + c], sc, sh);
    }
    node_emb[(size_t)n * H + c] = acc;
}

__global__ void pool_kernel(const float* __restrict__ node_emb, const int* __restrict__ batch,
                            float* __restrict__ gsum, float* __restrict__ cnt)
{
    int n = blockIdx.x;
    int c = threadIdx.x;
    int b = batch[n];
    atomicAdd(gsum + (size_t)b * H + c, node_emb[(size_t)n * H + c]);
    if (c == 0) atomicAdd(&cnt[b], 1.0f);
}

__global__ void predict_kernel(const float* __restrict__ gsum, const float* __restrict__ cnt,
                               const float* __restrict__ Wp, const float* __restrict__ bp,
                               float* __restrict__ out)
{
    int g = blockIdx.x, c = threadIdx.x;
    float v = gsum[(size_t)g * H + c] * Wp[c];
    __shared__ float red[8];
#pragma unroll
    for (int o = 16; o > 0; o >>= 1) v += __shfl_down_sync(0xffffffffu, v, o);
    if ((c & 31) == 0) red[c >> 5] = v;
    __syncthreads();
    if (c == 0) {
        float t = 0.f;
#pragma unroll
        for (int i = 0; i < 8; i++) t += red[i];
        out[g] = t / fmaxf(cnt[g], 1.0f) + bp[0];
    }
}

// -------------------------------------------------------------------------------
static void* symA(const void* sym)
{
    void* p = nullptr;
    cudaGetSymbolAddress(&p, sym);
    return p;
}

static void build_csr(const int* dst, int n, int E, int* deg, int* blk,
                      int* rowptr, int* cursor, int* eidx)
{
    int nb = (n + 255) / 256;
    zero_int_kernel<<<nb, 256>>>(deg, n);
    hist_kernel<<<(E + 255) / 256, 256>>>(dst, deg, E);
    scan_block_sums<<<nb, 256>>>(deg, blk, n);
    scan_single_block<<<1, 1024>>>(blk, nb);
    scan_final<<<nb, 256>>>(deg, blk, rowptr, cursor, n, E);
    fill_csr_kernel<<<(E + 255) / 256, 256>>>(dst, cursor, eidx, E);
}

extern "C" void kernel_launch(void* const* d_in, const int* in_sizes, int n_in,
                              void* d_out, int out_size)
{
    const float* x_g       = (const float*)d_in[0];
    const float* ea_g      = (const float*)d_in[1];
    const float* x_lg      = (const float*)d_in[2];
    const float* edb       = (const float*)d_in[3];
    const float* ea_lg     = (const float*)d_in[4];
    const float* W_enc     = (const float*)d_in[5];
    const float* b_enc     = (const float*)d_in[6];
    const float* W_msg     = (const float*)d_in[7];
    const float* b_msg     = (const float*)d_in[8];
    const float* Wg_nb     = (const float*)d_in[9];
    const float* bg_nb     = (const float*)d_in[10];
    const float* Wg_eb     = (const float*)d_in[11];
    const float* bg_eb     = (const float*)d_in[12];
    const float* Wl_nb     = (const float*)d_in[13];
    const float* bl_nb     = (const float*)d_in[14];
    const float* Wl_eb     = (const float*)d_in[15];
    const float* bl_eb     = (const float*)d_in[16];
    const float* W1        = (const float*)d_in[17];
    const float* b1        = (const float*)d_in[18];
    const float* W2        = (const float*)d_in[19];
    const float* b2        = (const float*)d_in[20];
    const float* bn_gamma  = (const float*)d_in[21];
    const float* bn_beta   = (const float*)d_in[22];
    const float* W_pred    = (const float*)d_in[23];
    const float* b_pred    = (const float*)d_in[24];
    const int*   eig       = (const int*)d_in[25];
    const int*   eil       = (const int*)d_in[26];
    const int*   batch     = (const int*)d_in[27];

    int N   = in_sizes[0] / 16;   // 20000
    int Eg  = in_sizes[1] / 16;   // 200000
    int Elg = in_sizes[4] / 4;    // 400000
    const int L = 4;

    cudaFuncSetAttribute(mma_gemm_kernel, cudaFuncAttributeMaxDynamicSharedMemorySize,
                         GEMM_SMEM);

    float* p_AB   = (float*)symA(g_AB);
    float* p_h    = (float*)symA(g_h);
    float* p_nbg  = (float*)symA(g_nbg);
    float* p_ebg  = (float*)symA(g_ebg);
    float* p_ne   = (float*)symA(g_nodeemb);
    double* p_bnacc = (double*)symA(g_bnacc);
    float* p_bnsc = (float*)symA(g_bnscale);
    float* p_bnsh = (float*)symA(g_bnshift);
    float* p_gsum = (float*)symA(g_gsum);
    float* p_cnt  = (float*)symA(g_cnt);

    int* p_deg    = (int*)symA(g_deg);
    int* p_cursor = (int*)symA(g_cursor);
    int* p_blk    = (int*)symA(g_blk);
    int* p_rp_lg  = (int*)symA(g_rowptr_lg);
    int* p_ei_lg  = (int*)symA(g_eidx_lg);
    int* p_rp_g   = (int*)symA(g_rowptr_g);
    int* p_ei_g   = (int*)symA(g_eidx_g);

    __nv_bfloat16* p_node_hi = (__nv_bfloat16*)symA(g_node_hi);
    __nv_bfloat16* p_node_lo = (__nv_bfloat16*)symA(g_node_lo);
    __nv_bfloat16* p_act_hi  = (__nv_bfloat16*)symA(g_act_hi);
    __nv_bfloat16* p_act_lo  = (__nv_bfloat16*)symA(g_act_lo);
    __nv_bfloat16* p_hid_hi  = (__nv_bfloat16*)symA(g_hid_hi);
    __nv_bfloat16* p_hid_lo  = (__nv_bfloat16*)symA(g_hid_lo);
    __nv_bfloat16* p_wthi    = (__nv_bfloat16*)symA(g_wthi);
    __nv_bfloat16* p_wtlo    = (__nv_bfloat16*)symA(g_wtlo);

    const int* src_g = eig;
    const int* dst_g = eig + Eg;
    const int* src_l = eil;
    const int* dst_l = eil + Elg;

    int mtE = (Eg + 127) / 128;   // 1563
    int mtN = (N + 127) / 128;    // 157

    // --- CSR builds (line graph by dst; graph edges by dst node) ---
    build_csr(dst_l, Eg, Elg, p_deg, p_blk, p_rp_lg, p_cursor, p_ei_lg);
    build_csr(dst_g, N, Eg, p_deg, p_blk, p_rp_g, p_cursor, p_ei_g);

    // --- weight transpose + split ---
    tsplit_kernel<<<(65536 + 255) / 256, 256>>>(W_msg,           p_wthi + OFF_WMSG,         p_wtlo + OFF_WMSG,         256, 256);
    tsplit_kernel<<<(65536 + 255) / 256, 256>>>(W_msg + 256 * H, p_wthi + OFF_WMSG + 65536, p_wtlo + OFF_WMSG + 65536, 256, 256);
    for (int l = 0; l < L; l++) {
        tsplit_kernel<<<(131072 + 255) / 256, 256>>>(
            W1 + (size_t)l * 131072, p_wthi + OFF_W1T + l * 131072, p_wtlo + OFF_W1T + l * 131072, 256, 512);
        tsplit_kernel<<<(131072 + 255) / 256, 256>>>(
            W2 + (size_t)l * 131072, p_wthi + OFF_W2T + l * 131072, p_wtlo + OFF_W2T + l * 131072, 512, 256);
    }

    // --- node encoder + combined msg GEMM (N=512) ---
    enc_kernel<<<N, 256>>>(x_g, W_enc, b_enc, p_node_hi, p_node_lo);
    {
        dim3 grid(mtN, 4);
        mma_gemm_kernel<<<grid, 256, GEMM_SMEM>>>(
            p_node_hi, p_node_lo, p_wthi + OFF_WMSG, p_wtlo + OFF_WMSG,
            nullptr, nullptr, p_AB, nullptr, nullptr, N, 512, 256, 0);
    }
    basis4_kernel<<<(Eg + 255) / 256, 256>>>(edb,   Wg_nb, bg_nb, p_nbg, Eg);
    basis4_kernel<<<(Elg + 255) / 256, 256>>>(ea_lg, Wg_eb, bg_eb, p_ebg, Elg);
    msg_edge_kernel<<<(Eg + MEPB - 1) / MEPB, 256>>>(
        p_AB, ea_g, x_lg, W_msg + 512 * H, W_msg + 528 * H, b_msg,
        src_g, dst_g, p_h, Eg);

    // --- 4 GENConv layers ---
    for (int l = 0; l < L; l++) {
        int use_bn = (l > 0) ? 1 : 0;
        if (use_bn) {
            cudaMemsetAsync(p_bnacc, 0, 2 * H * sizeof(double));
            bn_stats_kernel<<<1024, 256>>>(p_h, Eg, p_bnacc);
            bn_coef_kernel<<<1, 256>>>(p_bnacc, bn_gamma + (l - 1) * H, bn_beta + (l - 1) * H,
                                       p_bnsc, p_bnsh, Eg);
        }
        gen_aggr_kernel<<<Eg, 256>>>(
            p_h, p_nbg, p_ebg,
            Wl_nb + l * 4 * H, bl_nb + l * H,
            Wl_eb + l * 4 * H, bl_eb + l * H,
            p_bnsc, p_bnsh, src_l, p_rp_lg, p_ei_lg,
            p_act_hi, p_act_lo, use_bn);

        // GEMM1: hidden = relu(hpre @ W1 + b1), split bf16 out
        {
            dim3 grid(mtE, 4);
            mma_gemm_kernel<<<grid, 256, GEMM_SMEM>>>(
                p_act_hi, p_act_lo, p_wthi + OFF_W1T + l * 131072, p_wtlo + OFF_W1T + l * 131072,
                b1 + l * 512, nullptr, nullptr, p_hid_hi, p_hid_lo,
                Eg, 512, 256, 1 | 2 | 8);
        }
        // GEMM2: h = hidden @ W2 + b2 (+ residual for l>0), fp32 out
        {
            dim3 grid(mtE, 2);
            mma_gemm_kernel<<<grid, 256, GEMM_SMEM>>>(
                p_hid_hi, p_hid_lo, p_wthi + OFF_W2T + l * 131072, p_wtlo + OFF_W2T + l * 131072,
                b2 + l * 256, (l > 0) ? p_h : nullptr, p_h, nullptr, nullptr,
                Eg, 256, 512, (l > 0) ? (1 | 4) : 1);
        }
    }

    // --- final BN coefs + CSR node gather ---
    cudaMemsetAsync(p_bnacc, 0, 2 * H * sizeof(double));
    bn_stats_kernel<<<1024, 256>>>(p_h, Eg, p_bnacc);
    bn_coef_kernel<<<1, 256>>>(p_bnacc, bn_gamma + 3 * H, bn_beta + 3 * H, p_bnsc, p_bnsh, Eg);

    node_gather_kernel<<<N, 256>>>(p_h, p_bnsc, p_bnsh, p_rp_g, p_ei_g, p_ne);

    cudaMemsetAsync(p_gsum, 0, NGRAPH * H * sizeof(float));
    cudaMemsetAsync(p_cnt,  0, NGRAPH * sizeof(float));
    pool_kernel<<<N, 256>>>(p_ne, batch, p_gsum, p_cnt);
    predict_kernel<<<NGRAPH, 256>>>(p_gsum, p_cnt, W_pred, b_pred, (float*)d_out);
}

// round 7
// speedup vs baseline: 2.5639x; 1.1989x over previous
#include <cuda_runtime.h>
#include <cuda_fp16.h>
#include <cstdint>

#define H 256
#define NGRAPH 128
#define MAXN   20224
#define MAXEG  200192
#define MAXELG 400128

// ---------------- scratch ----------------
__device__ float g_AB[(size_t)MAXN * 512];
__device__ float g_h[(size_t)MAXEG * H];
__device__ float g_nbg[(size_t)MAXEG * 4];
__device__ float g_ebg[(size_t)MAXELG * 4];
__device__ float g_nodeemb[(size_t)MAXN * H];
__device__ double g_bnacc[2 * H];
__device__ float g_bnscale[H];
__device__ float g_bnshift[H];
__device__ float g_gsum[NGRAPH * H];
__device__ float g_cnt[NGRAPH];

// CSR scratch
__device__ int g_deg[MAXEG];
__device__ int g_cursor[MAXEG];
__device__ int g_blk[1024];
__device__ int g_rowptr_lg[MAXEG + 1];
__device__ int g_eidx_lg[MAXELG];
__device__ int g_rowptr_g[MAXN + 1];
__device__ int g_eidx_g[MAXEG];

// fp16 activation buffers (pad rows beyond M never written -> stay zero)
__device__ __half g_node[(size_t)MAXN * H];
__device__ __half g_act[(size_t)MAXEG * H];
__device__ __half g_hid[(size_t)MAXEG * 2 * H];

// transposed/split fp16 weights arena
#define OFF_WMSG 0
#define OFF_W1T  (512 * 256)
#define OFF_W2T  (OFF_W1T + 4 * 131072)
#define WT_TOTAL (OFF_W2T + 4 * 131072)
__device__ __half g_wthi[WT_TOTAL];
__device__ __half g_wtlo[WT_TOTAL];

// ======================= helpers =======================
__device__ __forceinline__ uint32_t smem_u32(const void* p) {
    uint32_t a;
    asm("{ .reg .u64 t; cvta.to.shared.u64 t, %1; cvt.u32.u64 %0, t; }" : "=r"(a) : "l"(p));
    return a;
}
#define CP16(dst, src) \
    asm volatile("cp.async.cg.shared.global [%0], [%1], 16;" :: "r"(dst), "l"(src) : "memory")
#define CP_COMMIT() asm volatile("cp.async.commit_group;" ::: "memory")
#define CP_WAIT1()  asm volatile("cp.async.wait_group 1;" ::: "memory")
#define CP_WAIT0()  asm volatile("cp.async.wait_group 0;" ::: "memory")

__device__ __forceinline__ void ldm4(uint32_t (&r)[4], uint32_t addr) {
    asm volatile("ldmatrix.sync.aligned.m8n8.x4.shared.b16 {%0,%1,%2,%3}, [%4];"
                 : "=r"(r[0]), "=r"(r[1]), "=r"(r[2]), "=r"(r[3]) : "r"(addr));
}
__device__ __forceinline__ void mma_f16(float (&d)[4], const uint32_t (&a)[4], const uint32_t* b) {
    asm volatile(
        "mma.sync.aligned.m16n8k16.row.col.f32.f16.f16.f32 "
        "{%0,%1,%2,%3}, {%4,%5,%6,%7}, {%8,%9}, {%0,%1,%2,%3};"
        : "+f"(d[0]), "+f"(d[1]), "+f"(d[2]), "+f"(d[3])
        : "r"(a[0]), "r"(a[1]), "r"(a[2]), "r"(a[3]), "r"(b[0]), "r"(b[1]));
}

// ======================= CSR build kernels =======================
__global__ void zero_int_kernel(int* a, int n)
{
    int i = blockIdx.x * 256 + threadIdx.x;
    if (i < n) a[i] = 0;
}
__global__ void hist_kernel(const int* __restrict__ dst, int* __restrict__ deg, int E)
{
    int i = blockIdx.x * 256 + threadIdx.x;
    if (i < E) atomicAdd(&deg[dst[i]], 1);
}
__global__ void scan_block_sums(const int* __restrict__ deg, int* __restrict__ blk, int n)
{
    __shared__ int sd[256];
    int t = threadIdx.x;
    int i = blockIdx.x * 256 + t;
    sd[t] = (i < n) ? deg[i] : 0;
    __syncthreads();
    for (int o = 128; o > 0; o >>= 1) {
        if (t < o) sd[t] += sd[t + o];
        __syncthreads();
    }
    if (t == 0) blk[blockIdx.x] = sd[0];
}
__global__ void scan_single_block(int* blk, int nb)
{
    __shared__ int tmp[1024];
    int t = threadIdx.x;
    int v = (t < nb) ? blk[t] : 0;
    tmp[t] = v;
    __syncthreads();
    for (int o = 1; o < 1024; o <<= 1) {
        int u = (t >= o) ? tmp[t - o] : 0;
        __syncthreads();
        tmp[t] += u;
        __syncthreads();
    }
    if (t < nb) blk[t] = tmp[t] - v;
}
__global__ void scan_final(const int* __restrict__ deg, const int* __restrict__ blk,
                           int* __restrict__ rowptr, int* __restrict__ cursor, int n, int E)
{
    __shared__ int tmp[256];
    int t = threadIdx.x;
    int i = blockIdx.x * 256 + t;
    int v = (i < n) ? deg[i] : 0;
    tmp[t] = v;
    __syncthreads();
    for (int o = 1; o < 256; o <<= 1) {
        int u = (t >= o) ? tmp[t - o] : 0;
        __syncthreads();
        tmp[t] += u;
        __syncthreads();
    }
    int excl = tmp[t] - v + blk[blockIdx.x];
    if (i < n) { rowptr[i] = excl; cursor[i] = excl; }
    if (blockIdx.x == 0 && t == 0) rowptr[n] = E;
}
__global__ void fill_csr_kernel(const int* __restrict__ dst, int* __restrict__ cursor,
                                int* __restrict__ eidx, int E)
{
    int e = blockIdx.x * 256 + threadIdx.x;
    if (e < E) {
        int p = atomicAdd(&cursor[dst[e]], 1);
        eidx[p] = e;
    }
}

// ======================= mma.sync 2-term fp16 GEMM =======================
// C[M,N] = A[M,K] @ W[K,N]; A fp16 [M,K] row-major, W transposed split fp16
// (Bhi,Blo) [N,K] row-major.  C = A*Bhi + A*Blo (fp32 acc).
// CTA 128x128, 8 warps of 64x32, BK=32, 3 stages, 2 CTAs/SM.
// flags: 1=bias, 2=relu, 4=residual(fp32 [M,N]), 8=fp16 out (else fp32 out)
#define RB 80
#define TILE_B (128 * RB)
#define SO_A   0
#define SO_BHI (1 * TILE_B)
#define SO_BLO (2 * TILE_B)
#define STAGE_B (3 * TILE_B)        // 30720
#define GEMM_SMEM (3 * STAGE_B)     // 92160

__device__ __forceinline__ void load_stage(uint32_t sbase,
    const __half* __restrict__ A, const __half* __restrict__ B_hi,
    const __half* __restrict__ B_lo,
    int K, int m0, int n0, int k0, int tid)
{
#pragma unroll
    for (int i = 0; i < 2; i++) {
        int g = tid + i * 256;
        int row = g >> 2, ch = g & 3;
        uint32_t so = (uint32_t)row * RB + (uint32_t)ch * 16;
        size_t ao = (size_t)(m0 + row) * K + k0 + ch * 8;
        size_t bo = (size_t)(n0 + row) * K + k0 + ch * 8;
        CP16(sbase + SO_A + so, A + ao);
        CP16(sbase + SO_BHI + so, B_hi + bo);
        CP16(sbase + SO_BLO + so, B_lo + bo);
    }
}

__global__ __launch_bounds__(256, 2) void mma_gemm_kernel(
    const __half* __restrict__ A,
    const __half* __restrict__ Bhi, const __half* __restrict__ Blo,
    const float* __restrict__ bias, const float* __restrict__ res,
    float* __restrict__ Cf, __half* __restrict__ Ch,
    int M, int N, int K, int flags)
{
    extern __shared__ __align__(128) char smem[];
    uint32_t sb = smem_u32(smem);
    int tid = threadIdx.x;
    int wid = tid >> 5, lane = tid & 31;
    int m0 = blockIdx.x * 128, n0 = blockIdx.y * 128;
    int nk = K >> 5;

    load_stage(sb, A, Bhi, Blo, K, m0, n0, 0, tid);
    CP_COMMIT();
    load_stage(sb + STAGE_B, A, Bhi, Blo, K, m0, n0, 32, tid);
    CP_COMMIT();

    float acc[4][4][4];
#pragma unroll
    for (int i = 0; i < 4; i++)
#pragma unroll
        for (int j = 0; j < 4; j++)
#pragma unroll
            for (int q = 0; q < 4; q++) acc[i][j][q] = 0.f;

    int mo = (wid & 1) * 64, no = (wid >> 1) * 32;
    int a_row = mo + (lane & 15);
    int a_k8  = lane >> 4;
    int b_row = ((lane >> 4) << 3) + (lane & 7);
    int b_k8  = (lane >> 3) & 1;

    for (int k = 0; k < nk; k++) {
        if (k == nk - 1) { CP_WAIT0(); } else { CP_WAIT1(); }
        __syncthreads();
        uint32_t base = sb + (uint32_t)(k % 3) * STAGE_B;
        if (k + 2 < nk)
            load_stage(sb + (uint32_t)((k + 2) % 3) * STAGE_B, A, Bhi, Blo,
                       K, m0, n0, (k + 2) * 32, tid);
        CP_COMMIT();
#pragma unroll
        for (int k16 = 0; k16 < 2; k16++) {
            int kk8 = k16 * 2;
            uint32_t ah[4][4];
#pragma unroll
            for (int i = 0; i < 4; i++) {
                uint32_t aaddr = base + SO_A + (uint32_t)(a_row + i * 16) * RB
                               + (uint32_t)(kk8 + a_k8) * 16;
                ldm4(ah[i], aaddr);
            }
#pragma unroll
            for (int j = 0; j < 2; j++) {
                uint32_t bh[4], bl[4];
                uint32_t baddr = base + SO_BHI + (uint32_t)(no + j * 16 + b_row) * RB
                               + (uint32_t)(kk8 + b_k8) * 16;
                ldm4(bh, baddr);
                ldm4(bl, baddr + (SO_BLO - SO_BHI));
#pragma unroll
                for (int i = 0; i < 4; i++) {
                    mma_f16(acc[i][2 * j],     ah[i], &bh[0]);
                    mma_f16(acc[i][2 * j + 1], ah[i], &bh[2]);
                    mma_f16(acc[i][2 * j],     ah[i], &bl[0]);
                    mma_f16(acc[i][2 * j + 1], ah[i], &bl[2]);
                }
            }
        }
    }

    // epilogue
#pragma unroll
    for (int i = 0; i < 4; i++) {
        int r0 = m0 + mo + i * 16 + (lane >> 2);
#pragma unroll
        for (int half = 0; half < 2; half++) {
            int r = r0 + half * 8;
            if (r >= M) continue;
#pragma unroll
            for (int nb = 0; nb < 4; nb++) {
                int col = n0 + no + nb * 8 + 2 * (lane & 3);
                float v0 = acc[i][nb][half * 2 + 0];
                float v1 = acc[i][nb][half * 2 + 1];
                if (flags & 1) { v0 += bias[col]; v1 += bias[col + 1]; }
                if (flags & 4) {
                    float2 t = *(const float2*)(res + (size_t)r * N + col);
                    v0 += t.x; v1 += t.y;
                }
                if (flags & 2) { v0 = fmaxf(v0, 0.f); v1 = fmaxf(v1, 0.f); }
                if (flags & 8) {
                    *(__half2*)(Ch + (size_t)r * N + col) =
                        __halves2half2(__float2half(v0), __float2half(v1));
                } else {
                    *(float2*)(Cf + (size_t)r * N + col) = make_float2(v0, v1);
                }
            }
        }
    }
}

// ---------------- weight transpose+split (fp16 hi/lo) --------------------------
__global__ void tsplit_kernel(const float* __restrict__ W,
                              __half* __restrict__ thi, __half* __restrict__ tlo,
                              int K, int N)
{
    int idx = blockIdx.x * 256 + threadIdx.x;
    if (idx >= K * N) return;
    int k = idx / N, n = idx % N;
    float w = W[idx];
    __half hi = __float2half(w);
    __half lo = __float2half(w - __half2float(hi));
    thi[(size_t)n * K + k] = hi;
    tlo[(size_t)n * K + k] = lo;
}

// ---------------- node encoder (fp16 out) --------------------------------------
__global__ void enc_kernel(const float* __restrict__ xg, const float* __restrict__ W,
                           const float* __restrict__ b, __half* __restrict__ out)
{
    __shared__ float sx[16];
    int n = blockIdx.x, c = threadIdx.x;
    if (c < 16) sx[c] = xg[(size_t)n * 16 + c];
    __syncthreads();
    float v = b[c];
#pragma unroll
    for (int k = 0; k < 16; k++) v = fmaf(sx[k], W[k * H + c], v);
    out[(size_t)n * H + c] = __float2half(v);
}

// ---------------- tiny [E,4]@[4,4]+b projection --------------------------------
__global__ void basis4_kernel(const float* __restrict__ in, const float* __restrict__ W,
                              const float* __restrict__ b, float* __restrict__ out, int E)
{
    int e = blockIdx.x * blockDim.x + threadIdx.x;
    if (e >= E) return;
    float4 x = *(const float4*)(in + (size_t)e * 4);
    float o0 = b[0] + x.x * W[0] + x.y * W[4] + x.z * W[8]  + x.w * W[12];
    float o1 = b[1] + x.x * W[1] + x.y * W[5] + x.z * W[9]  + x.w * W[13];
    float o2 = b[2] + x.x * W[2] + x.y * W[6] + x.z * W[10] + x.w * W[14];
    float o3 = b[3] + x.x * W[3] + x.y * W[7] + x.z * W[11] + x.w * W[15];
    *(float4*)(out + (size_t)e * 4) = make_float4(o0, o1, o2, o3);
}

// ---------------- fused first-message ------------------------------------------
#define MEPB 16
__global__ __launch_bounds__(256) void msg_edge_kernel(
    const float* __restrict__ AB,
    const float* __restrict__ ea, const float* __restrict__ xlg,
    const float* __restrict__ Wc, const float* __restrict__ Wd,
    const float* __restrict__ bmsg,
    const int* __restrict__ srcg, const int* __restrict__ dstg,
    float* __restrict__ h, int Eg)
{
    __shared__ float sWc[16 * H];
    __shared__ float sWd[4 * H];
    __shared__ float sb[H];
    __shared__ float sea[MEPB][16];
    __shared__ float sxl[MEPB][4];
    int tid = threadIdx.x;
    for (int i = tid; i < 16 * H; i += 256) sWc[i] = Wc[i];
    for (int i = tid; i < 4 * H; i += 256) sWd[i] = Wd[i];
    sb[tid] = bmsg[tid];
    int e0 = blockIdx.x * MEPB;
    for (int i = tid; i < MEPB * 16; i += 256) {
        int e = e0 + i / 16;
        if (e < Eg) sea[i / 16][i % 16] = ea[(size_t)e * 16 + (i % 16)];
    }
    for (int i = tid; i < MEPB * 4; i += 256) {
        int e = e0 + i / 4;
        if (e < Eg) sxl[i / 4][i % 4] = xlg[(size_t)e * 4 + (i % 4)];
    }
    __syncthreads();
    int c = tid;
    for (int i = 0; i < MEPB; i++) {
        int e = e0 + i;
        if (e >= Eg) break;
        int s = srcg[e], d = dstg[e];
        float v = AB[(size_t)s * 512 + c] + AB[(size_t)d * 512 + 256 + c] + sb[c];
#pragma unroll
        for (int k = 0; k < 16; k++) v = fmaf(sea[i][k], sWc[k * H + c], v);
#pragma unroll
        for (int k = 0; k < 4; k++) v = fmaf(sxl[i][k], sWd[k * H + c], v);
        h[(size_t)e * H + c] = v;
    }
}

// ---------------- BN coefficient computation -----------------------------------
__global__ void bn_coef_kernel(const double* __restrict__ acc,
                               const float* __restrict__ gamma, const float* __restrict__ beta,
                               float* __restrict__ scale, float* __restrict__ shift, int M)
{
    int c = threadIdx.x;
    double mu = acc[c] / (double)M;
    double var = acc[H + c] / (double)M - mu * mu;
    float inv = rsqrtf((float)var + 1e-5f);
    float sc = gamma[c] * inv;
    scale[c] = sc;
    shift[c] = beta[c] - (float)mu * sc;
}

// ---------------- fused GENConv aggregation (CSR gather, fp16 out) -------------
__global__ __launch_bounds__(256) void gen_aggr_kernel(
    const float* __restrict__ x, const float* __restrict__ nbg, const float* __restrict__ ebg,
    const float* __restrict__ Wnb, const float* __restrict__ bnb,
    const float* __restrict__ Web, const float* __restrict__ beb,
    const float* __restrict__ bnscale, const float* __restrict__ bnshift,
    const int* __restrict__ src, const int* __restrict__ rowptr, const int* __restrict__ eidx,
    __half* __restrict__ aout, int use_bn)
{
    __shared__ float sWn[4 * H], sWe[4 * H], sbn[H], sbe[H];
    int tid = threadIdx.x;
    for (int i = tid; i < 4 * H; i += 256) { sWn[i] = Wnb[i]; sWe[i] = Web[i]; }
    sbn[tid] = bnb[tid];
    sbe[tid] = beb[tid];
    __syncthreads();
    int d = blockIdx.x, c = tid;
    float sc = 1.f, sh = 0.f;
    if (use_bn) { sc = bnscale[c]; sh = bnshift[c]; }
    int beg = rowptr[d], end = rowptr[d + 1];
    float se = 0.f, sw = 0.f;
    for (int p = beg; p < end; p++) {
        int e = eidx[p];
        int s = src[e];
        float4 nv = *(const float4*)(nbg + (size_t)s * 4);
        float4 ev4 = *(const float4*)(ebg + (size_t)e * 4);
        float nbv = sbn[c];
        nbv = fmaf(nv.x, sWn[c], nbv);
        nbv = fmaf(nv.y, sWn[H + c], nbv);
        nbv = fmaf(nv.z, sWn[2 * H + c], nbv);
        nbv = fmaf(nv.w, sWn[3 * H + c], nbv);
        float ebv = sbe[c];
        ebv = fmaf(ev4.x, sWe[c], ebv);
        ebv = fmaf(ev4.y, sWe[H + c], ebv);
        ebv = fmaf(ev4.z, sWe[2 * H + c], ebv);
        ebv = fmaf(ev4.w, sWe[3 * H + c], ebv);
        float xv = x[(size_t)s * H + c];
        if (use_bn) xv = fmaxf(fmaf(xv, sc, sh), 0.f);
        float mv = fmaxf(xv + nbv + ebv, 0.f) + 1e-7f;
        float ee = expf(fminf(mv, 80.f));
        se += ee;
        sw += ee * mv;
    }
    float xv = x[(size_t)d * H + c];
    if (use_bn) xv = fmaxf(fmaf(xv, sc, sh), 0.f);
    float v = xv + sw / (se + 1e-16f);
    aout[(size_t)d * H + c] = __float2half(v);
}

// ---------------- BatchNorm statistics -----------------------------------------
__global__ void bn_stats_kernel(const float* __restrict__ h, int M, double* __restrict__ acc)
{
    int c = threadIdx.x;
    float s = 0.f, s2 = 0.f;
    for (int r = blockIdx.x; r < M; r += gridDim.x) {
        float v = h[(size_t)r * H + c];
        s += v;
        s2 = fmaf(v, v, s2);
    }
    atomicAdd(&acc[c], (double)s);
    atomicAdd(&acc[H + c], (double)s2);
}

// ---------------- node gather (BN fused, CSR over dst_g) -----------------------
__global__ void node_gather_kernel(const float* __restrict__ h,
                                   const float* __restrict__ bnscale,
                                   const float* __restrict__ bnshift,
                                   const int* __restrict__ rowptr, const int* __restrict__ eidx,
                                   float* __restrict__ node_emb)
{
    int n = blockIdx.x, c = threadIdx.x;
    float sc = bnscale[c], sh = bnshift[c];
    int beg = rowptr[n], end = rowptr[n + 1];
    float acc = 0.f;
    for (int p = beg; p < end; p++) {
        int e = eidx[p];
        acc += fmaf(h[(size_t)e * H + c], sc, sh);
    }
    node_emb[(size_t)n * H + c] = acc;
}

__global__ void pool_kernel(const float* __restrict__ node_emb, const int* __restrict__ batch,
                            float* __restrict__ gsum, float* __restrict__ cnt)
{
    int n = blockIdx.x;
    int c = threadIdx.x;
    int b = batch[n];
    atomicAdd(gsum + (size_t)b * H + c, node_emb[(size_t)n * H + c]);
    if (c == 0) atomicAdd(&cnt[b], 1.0f);
}

__global__ void predict_kernel(const float* __restrict__ gsum, const float* __restrict__ cnt,
                               const float* __restrict__ Wp, const float* __restrict__ bp,
                               float* __restrict__ out)
{
    int g = blockIdx.x, c = threadIdx.x;
    float v = gsum[(size_t)g * H + c] * Wp[c];
    __shared__ float red[8];
#pragma unroll
    for (int o = 16; o > 0; o >>= 1) v += __shfl_down_sync(0xffffffffu, v, o);
    if ((c & 31) == 0) red[c >> 5] = v;
    __syncthreads();
    if (c == 0) {
        float t = 0.f;
#pragma unroll
        for (int i = 0; i < 8; i++) t += red[i];
        out[g] = t / fmaxf(cnt[g], 1.0f) + bp[0];
    }
}

// -------------------------------------------------------------------------------
static void* symA(const void* sym)
{
    void* p = nullptr;
    cudaGetSymbolAddress(&p, sym);
    return p;
}

static void build_csr(const int* dst, int n, int E, int* deg, int* blk,
                      int* rowptr, int* cursor, int* eidx)
{
    int nb = (n + 255) / 256;
    zero_int_kernel<<<nb, 256>>>(deg, n);
    hist_kernel<<<(E + 255) / 256, 256>>>(dst, deg, E);
    scan_block_sums<<<nb, 256>>>(deg, blk, n);
    scan_single_block<<<1, 1024>>>(blk, nb);
    scan_final<<<nb, 256>>>(deg, blk, rowptr, cursor, n, E);
    fill_csr_kernel<<<(E + 255) / 256, 256>>>(dst, cursor, eidx, E);
}

extern "C" void kernel_launch(void* const* d_in, const int* in_sizes, int n_in,
                              void* d_out, int out_size)
{
    const float* x_g       = (const float*)d_in[0];
    const float* ea_g      = (const float*)d_in[1];
    const float* x_lg      = (const float*)d_in[2];
    const float* edb       = (const float*)d_in[3];
    const float* ea_lg     = (const float*)d_in[4];
    const float* W_enc     = (const float*)d_in[5];
    const float* b_enc     = (const float*)d_in[6];
    const float* W_msg     = (const float*)d_in[7];
    const float* b_msg     = (const float*)d_in[8];
    const float* Wg_nb     = (const float*)d_in[9];
    const float* bg_nb     = (const float*)d_in[10];
    const float* Wg_eb     = (const float*)d_in[11];
    const float* bg_eb     = (const float*)d_in[12];
    const float* Wl_nb     = (const float*)d_in[13];
    const float* bl_nb     = (const float*)d_in[14];
    const float* Wl_eb     = (const float*)d_in[15];
    const float* bl_eb     = (const float*)d_in[16];
    const float* W1        = (const float*)d_in[17];
    const float* b1        = (const float*)d_in[18];
    const float* W2        = (const float*)d_in[19];
    const float* b2        = (const float*)d_in[20];
    const float* bn_gamma  = (const float*)d_in[21];
    const float* bn_beta   = (const float*)d_in[22];
    const float* W_pred    = (const float*)d_in[23];
    const float* b_pred    = (const float*)d_in[24];
    const int*   eig       = (const int*)d_in[25];
    const int*   eil       = (const int*)d_in[26];
    const int*   batch     = (const int*)d_in[27];

    int N   = in_sizes[0] / 16;   // 20000
    int Eg  = in_sizes[1] / 16;   // 200000
    int Elg = in_sizes[4] / 4;    // 400000
    const int L = 4;

    cudaFuncSetAttribute(mma_gemm_kernel, cudaFuncAttributeMaxDynamicSharedMemorySize,
                         GEMM_SMEM);

    float* p_AB   = (float*)symA(g_AB);
    float* p_h    = (float*)symA(g_h);
    float* p_nbg  = (float*)symA(g_nbg);
    float* p_ebg  = (float*)symA(g_ebg);
    float* p_ne   = (float*)symA(g_nodeemb);
    double* p_bnacc = (double*)symA(g_bnacc);
    float* p_bnsc = (float*)symA(g_bnscale);
    float* p_bnsh = (float*)symA(g_bnshift);
    float* p_gsum = (float*)symA(g_gsum);
    float* p_cnt  = (float*)symA(g_cnt);

    int* p_deg    = (int*)symA(g_deg);
    int* p_cursor = (int*)symA(g_cursor);
    int* p_blk    = (int*)symA(g_blk);
    int* p_rp_lg  = (int*)symA(g_rowptr_lg);
    int* p_ei_lg  = (int*)symA(g_eidx_lg);
    int* p_rp_g   = (int*)symA(g_rowptr_g);
    int* p_ei_g   = (int*)symA(g_eidx_g);

    __half* p_node = (__half*)symA(g_node);
    __half* p_act  = (__half*)symA(g_act);
    __half* p_hid  = (__half*)symA(g_hid);
    __half* p_wthi = (__half*)symA(g_wthi);
    __half* p_wtlo = (__half*)symA(g_wtlo);

    const int* src_g = eig;
    const int* dst_g = eig + Eg;
    const int* src_l = eil;
    const int* dst_l = eil + Elg;

    int mtE = (Eg + 127) / 128;   // 1563
    int mtN = (N + 127) / 128;    // 157

    // --- CSR builds ---
    build_csr(dst_l, Eg, Elg, p_deg, p_blk, p_rp_lg, p_cursor, p_ei_lg);
    build_csr(dst_g, N, Eg, p_deg, p_blk, p_rp_g, p_cursor, p_ei_g);

    // --- weight transpose + split ---
    tsplit_kernel<<<(65536 + 255) / 256, 256>>>(W_msg,           p_wthi + OFF_WMSG,         p_wtlo + OFF_WMSG,         256, 256);
    tsplit_kernel<<<(65536 + 255) / 256, 256>>>(W_msg + 256 * H, p_wthi + OFF_WMSG + 65536, p_wtlo + OFF_WMSG + 65536, 256, 256);
    for (int l = 0; l < L; l++) {
        tsplit_kernel<<<(131072 + 255) / 256, 256>>>(
            W1 + (size_t)l * 131072, p_wthi + OFF_W1T + l * 131072, p_wtlo + OFF_W1T + l * 131072, 256, 512);
        tsplit_kernel<<<(131072 + 255) / 256, 256>>>(
            W2 + (size_t)l * 131072, p_wthi + OFF_W2T + l * 131072, p_wtlo + OFF_W2T + l * 131072, 512, 256);
    }

    // --- node encoder + combined msg GEMM (N=512) ---
    enc_kernel<<<N, 256>>>(x_g, W_enc, b_enc, p_node);
    {
        dim3 grid(mtN, 4);
        mma_gemm_kernel<<<grid, 256, GEMM_SMEM>>>(
            p_node, p_wthi + OFF_WMSG, p_wtlo + OFF_WMSG,
            nullptr, nullptr, p_AB, nullptr, N, 512, 256, 0);
    }
    basis4_kernel<<<(Eg + 255) / 256, 256>>>(edb,   Wg_nb, bg_nb, p_nbg, Eg);
    basis4_kernel<<<(Elg + 255) / 256, 256>>>(ea_lg, Wg_eb, bg_eb, p_ebg, Elg);
    msg_edge_kernel<<<(Eg + MEPB - 1) / MEPB, 256>>>(
        p_AB, ea_g, x_lg, W_msg + 512 * H, W_msg + 528 * H, b_msg,
        src_g, dst_g, p_h, Eg);

    // --- 4 GENConv layers ---
    for (int l = 0; l < L; l++) {
        int use_bn = (l > 0) ? 1 : 0;
        if (use_bn) {
            cudaMemsetAsync(p_bnacc, 0, 2 * H * sizeof(double));
            bn_stats_kernel<<<1024, 256>>>(p_h, Eg, p_bnacc);
            bn_coef_kernel<<<1, 256>>>(p_bnacc, bn_gamma + (l - 1) * H, bn_beta + (l - 1) * H,
                                       p_bnsc, p_bnsh, Eg);
        }
        gen_aggr_kernel<<<Eg, 256>>>(
            p_h, p_nbg, p_ebg,
            Wl_nb + l * 4 * H, bl_nb + l * H,
            Wl_eb + l * 4 * H, bl_eb + l * H,
            p_bnsc, p_bnsh, src_l, p_rp_lg, p_ei_lg,
            p_act, use_bn);

        // GEMM1: hid = relu(act @ W1 + b1), fp16 out
        {
            dim3 grid(mtE, 4);
            mma_gemm_kernel<<<grid, 256, GEMM_SMEM>>>(
                p_act, p_wthi + OFF_W1T + l * 131072, p_wtlo + OFF_W1T + l * 131072,
                b1 + l * 512, nullptr, nullptr, p_hid,
                Eg, 512, 256, 1 | 2 | 8);
        }
        // GEMM2: h = hid @ W2 + b2 (+ residual for l>0), fp32 out
        {
            dim3 grid(mtE, 2);
            mma_gemm_kernel<<<grid, 256, GEMM_SMEM>>>(
                p_hid, p_wthi + OFF_W2T + l * 131072, p_wtlo + OFF_W2T + l * 131072,
                b2 + l * 256, (l > 0) ? p_h : nullptr, p_h, nullptr,
                Eg, 256, 512, (l > 0) ? (1 | 4) : 1);
        }
    }

    // --- final BN coefs + CSR node gather ---
    cudaMemsetAsync(p_bnacc, 0, 2 * H * sizeof(double));
    bn_stats_kernel<<<1024, 256>>>(p_h, Eg, p_bnacc);
    bn_coef_kernel<<<1, 256>>>(p_bnacc, bn_gamma + 3 * H, bn_beta + 3 * H, p_bnsc, p_bnsh, Eg);

    node_gather_kernel<<<N, 256>>>(p_h, p_bnsc, p_bnsh, p_rp_g, p_ei_g, p_ne);

    cudaMemsetAsync(p_gsum, 0, NGRAPH * H * sizeof(float));
    cudaMemsetAsync(p_cnt,  0, NGRAPH * sizeof(float));
    pool_kernel<<<N, 256>>>(p_ne, batch, p_gsum, p_cnt);
    predict_kernel<<<NGRAPH, 256>>>(p_gsum, p_cnt, W_pred, b_pred, (float*)d_out);
}